// round 3
// baseline (speedup 1.0000x reference)
#include <cuda_runtime.h>
#include <math.h>

#define BATCH 2
#define SEQ   1024
#define DIM   512
#define NH    8
#define HD    64
#define MROWS (BATCH*SEQ)      // 2048
#define CHK   32
#define NCHK  (SEQ/CHK)        // 32 chunks per (b) per head
#define NBH   (BATCH*NH)       // 16
#define NBLK  (NBH*NCHK)       // 512

// ---------------- scratch (no allocations allowed; __device__ globals) ------
__device__ float g_q  [MROWS*DIM];
__device__ float g_k  [MROWS*DIM];
__device__ float g_v  [MROWS*DIM];
__device__ float g_att[MROWS*DIM];
__device__ float g_o2 [MROWS*DIM];
__device__ float g_kv [NBLK*HD*HD];   // per-chunk sums, then exclusive prefix in place
__device__ float g_ks [NBLK*HD];      // per-chunk k sums, then exclusive prefix in place

__device__ __forceinline__ float fmap(float t) {
    // elu(t)+1 = t+1 (t>0) else exp(t)
    return t > 0.f ? t + 1.f : expf(t);
}

// ---------------- fused QKV GEMM: z selects (Wq->g_q, Wk->g_k, Wv->g_v) ----
// C = fmap?(x[2048,512] @ W[512,512]);  BM=BN=64, BK=16, 256 thr, 4x4 micro
__global__ __launch_bounds__(256)
void qkv_gemm_kernel(const float* __restrict__ X,
                     const float* __restrict__ Wq,
                     const float* __restrict__ Wk,
                     const float* __restrict__ Wv)
{
    __shared__ float As[16][64];
    __shared__ float Bs[16][64];
    const int tid  = threadIdx.x;
    const int tx   = tid & 15, ty = tid >> 4;
    const int row0 = blockIdx.y * 64;
    const int col0 = blockIdx.x * 64;
    const int z    = blockIdx.z;

    const float* __restrict__ Bw = (z == 0) ? Wq : (z == 1) ? Wk : Wv;
    float* __restrict__ Cc       = (z == 0) ? g_q : (z == 1) ? g_k : g_v;

    float acc[4][4];
#pragma unroll
    for (int i = 0; i < 4; i++)
#pragma unroll
        for (int j = 0; j < 4; j++) acc[i][j] = 0.f;

    const int lr = tid >> 2;          // A tile row   0..63
    const int lk = (tid & 3) << 2;    // A tile k     0,4,8,12
    const int bk = tid >> 4;          // B tile k row 0..15
    const int bn = (tid & 15) << 2;   // B tile col

    for (int k0 = 0; k0 < DIM; k0 += 16) {
        float4 av = *(const float4*)&X[(size_t)(row0 + lr) * DIM + k0 + lk];
        As[lk+0][lr] = av.x; As[lk+1][lr] = av.y;
        As[lk+2][lr] = av.z; As[lk+3][lr] = av.w;
        *(float4*)&Bs[bk][bn] =
            *(const float4*)&Bw[(size_t)(k0 + bk) * DIM + col0 + bn];
        __syncthreads();
#pragma unroll
        for (int kk = 0; kk < 16; kk++) {
            float4 a = *(const float4*)&As[kk][ty * 4];
            float4 b = *(const float4*)&Bs[kk][tx * 4];
            float ar[4] = {a.x, a.y, a.z, a.w};
            float br[4] = {b.x, b.y, b.z, b.w};
#pragma unroll
            for (int i = 0; i < 4; i++)
#pragma unroll
                for (int j = 0; j < 4; j++) acc[i][j] += ar[i] * br[j];
        }
        __syncthreads();
    }

#pragma unroll
    for (int i = 0; i < 4; i++) {
        int r = row0 + ty * 4 + i;
#pragma unroll
        for (int j = 0; j < 4; j++) {
            int c = col0 + tx * 4 + j;
            float v = acc[i][j];
            if (z != 2) v = fmap(v);      // q,k get feature map; v plain
            Cc[(size_t)r * DIM + c] = v;
        }
    }
}

// ---------------- O GEMM: g_o2 = g_att @ Wo + bo ----------------------------
__global__ __launch_bounds__(256)
void o_gemm_kernel(const float* __restrict__ Wo, const float* __restrict__ bias)
{
    __shared__ float As[16][64];
    __shared__ float Bs[16][64];
    const int tid  = threadIdx.x;
    const int tx   = tid & 15, ty = tid >> 4;
    const int row0 = blockIdx.y * 64;
    const int col0 = blockIdx.x * 64;

    float acc[4][4];
#pragma unroll
    for (int i = 0; i < 4; i++)
#pragma unroll
        for (int j = 0; j < 4; j++) acc[i][j] = 0.f;

    const int lr = tid >> 2;
    const int lk = (tid & 3) << 2;
    const int bk = tid >> 4;
    const int bn = (tid & 15) << 2;

    for (int k0 = 0; k0 < DIM; k0 += 16) {
        float4 av = *(const float4*)&g_att[(size_t)(row0 + lr) * DIM + k0 + lk];
        As[lk+0][lr] = av.x; As[lk+1][lr] = av.y;
        As[lk+2][lr] = av.z; As[lk+3][lr] = av.w;
        *(float4*)&Bs[bk][bn] =
            *(const float4*)&Wo[(size_t)(k0 + bk) * DIM + col0 + bn];
        __syncthreads();
#pragma unroll
        for (int kk = 0; kk < 16; kk++) {
            float4 a = *(const float4*)&As[kk][ty * 4];
            float4 b = *(const float4*)&Bs[kk][tx * 4];
            float ar[4] = {a.x, a.y, a.z, a.w};
            float br[4] = {b.x, b.y, b.z, b.w};
#pragma unroll
            for (int i = 0; i < 4; i++)
#pragma unroll
                for (int j = 0; j < 4; j++) acc[i][j] += ar[i] * br[j];
        }
        __syncthreads();
    }

#pragma unroll
    for (int i = 0; i < 4; i++) {
        int r = row0 + ty * 4 + i;
#pragma unroll
        for (int j = 0; j < 4; j++) {
            int c = col0 + tx * 4 + j;
            g_o2[(size_t)r * DIM + c] = acc[i][j] + bias[c];
        }
    }
}

// ---------------- gate GEMM: sigmoid([x,o2] @ Wg + bg), fused final ---------
__global__ __launch_bounds__(256)
void gate_kernel(const float* __restrict__ X,
                 const float* __restrict__ Wg, const float* __restrict__ bg,
                 float* __restrict__ Out)
{
    __shared__ float As[16][64];
    __shared__ float Bs[16][64];
    const int tid  = threadIdx.x;
    const int tx   = tid & 15, ty = tid >> 4;
    const int row0 = blockIdx.y * 64;
    const int col0 = blockIdx.x * 64;

    float acc[4][4];
#pragma unroll
    for (int i = 0; i < 4; i++)
#pragma unroll
        for (int j = 0; j < 4; j++) acc[i][j] = 0.f;

    const int lr = tid >> 2;
    const int lk = (tid & 3) << 2;
    const int bk = tid >> 4;
    const int bn = (tid & 15) << 2;

    for (int k0 = 0; k0 < 2 * DIM; k0 += 16) {
        const float* src = (k0 < DIM) ? X : g_o2;
        int kb = (k0 < DIM) ? k0 : k0 - DIM;
        float4 av = *(const float4*)&src[(size_t)(row0 + lr) * DIM + kb + lk];
        As[lk+0][lr] = av.x; As[lk+1][lr] = av.y;
        As[lk+2][lr] = av.z; As[lk+3][lr] = av.w;
        *(float4*)&Bs[bk][bn] =
            *(const float4*)&Wg[(size_t)(k0 + bk) * DIM + col0 + bn];
        __syncthreads();
#pragma unroll
        for (int kk = 0; kk < 16; kk++) {
            float4 a = *(const float4*)&As[kk][ty * 4];
            float4 b = *(const float4*)&Bs[kk][tx * 4];
            float ar[4] = {a.x, a.y, a.z, a.w};
            float br[4] = {b.x, b.y, b.z, b.w};
#pragma unroll
            for (int i = 0; i < 4; i++)
#pragma unroll
                for (int j = 0; j < 4; j++) acc[i][j] += ar[i] * br[j];
        }
        __syncthreads();
    }

#pragma unroll
    for (int i = 0; i < 4; i++) {
        int r = row0 + ty * 4 + i;
#pragma unroll
        for (int j = 0; j < 4; j++) {
            int c = col0 + tx * 4 + j;
            float z  = acc[i][j] + bg[c];
            float g  = 1.f / (1.f + expf(-z));
            float xv = X   [(size_t)r * DIM + c];
            float ov = g_o2[(size_t)r * DIM + c];
            Out[(size_t)r * DIM + c] = xv + g * (ov - xv);
        }
    }
}

// ---------------- phase A: per-chunk kv outer-product sums + k sums ---------
__global__ __launch_bounds__(256)
void chunk_sums_kernel()
{
    const int bid = blockIdx.x;             // bh*NCHK + c
    const int c   = bid % NCHK;
    const int bh  = bid / NCHK;
    const int h   = bh % NH;
    const int b   = bh / NH;
    const int row0 = b * SEQ + c * CHK;
    const int col  = h * HD;

    __shared__ float ks[CHK][HD];
    __shared__ float vs[CHK][HD];
    for (int i = threadIdx.x; i < CHK * HD; i += 256) {
        int t = i / HD, d = i % HD;
        ks[t][d] = g_k[(size_t)(row0 + t) * DIM + col + d];
        vs[t][d] = g_v[(size_t)(row0 + t) * DIM + col + d];
    }
    __syncthreads();

    const int base = bid * HD * HD;
    for (int i = threadIdx.x; i < HD * HD; i += 256) {
        int d = i / HD, e = i % HD;
        float acc = 0.f;
#pragma unroll 16
        for (int t = 0; t < CHK; t++) acc += ks[t][d] * vs[t][e];
        g_kv[base + i] = acc;
    }
    if (threadIdx.x < HD) {
        float acc = 0.f;
#pragma unroll 16
        for (int t = 0; t < CHK; t++) acc += ks[t][threadIdx.x];
        g_ks[bid * HD + threadIdx.x] = acc;
    }
}

// ---------------- phase B: exclusive prefix over chunks per (b,h), in place -
__global__ __launch_bounds__(256)
void prefix_kernel()
{
    const int bh = blockIdx.x;              // 0..15
    for (int i = threadIdx.x; i < HD * HD; i += 256) {
        float run = 0.f;
        for (int c = 0; c < NCHK; c++) {
            int idx = (bh * NCHK + c) * HD * HD + i;
            float t = g_kv[idx];
            g_kv[idx] = run;
            run += t;
        }
    }
    for (int i = threadIdx.x; i < HD; i += 256) {
        float run = 0.f;
        for (int c = 0; c < NCHK; c++) {
            int idx = (bh * NCHK + c) * HD + i;
            float t = g_ks[idx];
            g_ks[idx] = run;
            run += t;
        }
    }
}

// ---------------- phase C: intra-chunk causal attention ---------------------
__global__ __launch_bounds__(256)
void chunk_out_kernel()
{
    const int bid = blockIdx.x;
    const int c   = bid % NCHK;
    const int bh  = bid / NCHK;
    const int h   = bh % NH;
    const int b   = bh / NH;
    const int row0 = b * SEQ + c * CHK;
    const int col  = h * HD;

    __shared__ float qs[CHK][HD];
    __shared__ float ks[CHK][HD];
    __shared__ float vs[CHK][HD];
    __shared__ float kvp[HD][HD];
    __shared__ float Sc[CHK][CHK];
    __shared__ float kp[HD];
    __shared__ float den[CHK];

    for (int i = threadIdx.x; i < CHK * HD; i += 256) {
        int t = i / HD, d = i % HD;
        qs[t][d] = g_q[(size_t)(row0 + t) * DIM + col + d];
        ks[t][d] = g_k[(size_t)(row0 + t) * DIM + col + d];
        vs[t][d] = g_v[(size_t)(row0 + t) * DIM + col + d];
    }
    const int base = bid * HD * HD;
    for (int i = threadIdx.x; i < HD * HD; i += 256) {
        kvp[i / HD][i % HD] = g_kv[base + i];
    }
    if (threadIdx.x < HD) kp[threadIdx.x] = g_ks[bid * HD + threadIdx.x];
    __syncthreads();

    // causal scores S[s][t] = q_s . k_t  (t <= s), zero elsewhere
    for (int i = threadIdx.x; i < CHK * CHK; i += 256) {
        int s = i / CHK, t = i % CHK;
        float acc = 0.f;
        if (t <= s) {
#pragma unroll 16
            for (int d = 0; d < HD; d++) acc += qs[s][d] * ks[t][d];
        }
        Sc[s][t] = acc;
    }
    __syncthreads();

    // denominator per row
    if (threadIdx.x < CHK) {
        int s = threadIdx.x;
        float acc = 0.f;
#pragma unroll 16
        for (int d = 0; d < HD; d++) acc += qs[s][d] * kp[d];
#pragma unroll 8
        for (int t = 0; t < CHK; t++) acc += Sc[s][t];
        den[s] = acc + 1e-6f;
    }
    __syncthreads();

    // out[s][e] = (q_s @ kvp + S[s,:] @ v) / den[s]
    for (int i = threadIdx.x; i < CHK * HD; i += 256) {
        int s = i / HD, e = i % HD;
        float acc = 0.f;
#pragma unroll 16
        for (int d = 0; d < HD; d++) acc += qs[s][d] * kvp[d][e];
#pragma unroll 16
        for (int t = 0; t < CHK; t++) acc += Sc[s][t] * vs[t][e];
        g_att[(size_t)(row0 + s) * DIM + col + e] = acc / den[s];
    }
}

// ---------------- launcher: pure kernel launches, nothing else --------------
extern "C" void kernel_launch(void* const* d_in, const int* in_sizes, int n_in,
                              void* d_out, int out_size)
{
    const float* x  = (const float*)d_in[0];
    const float* Wq = (const float*)d_in[1];
    const float* Wk = (const float*)d_in[2];
    const float* Wv = (const float*)d_in[3];
    const float* Wo = (const float*)d_in[4];
    const float* bo = (const float*)d_in[5];
    const float* Wg = (const float*)d_in[6];
    const float* bg = (const float*)d_in[7];
    float* out = (float*)d_out;

    dim3 grid (DIM / 64, MROWS / 64, 1);   // (8, 32)
    dim3 grid3(DIM / 64, MROWS / 64, 3);   // fused QKV

    qkv_gemm_kernel<<<grid3, 256>>>(x, Wq, Wk, Wv);
    chunk_sums_kernel<<<NBLK, 256>>>();
    prefix_kernel<<<NBH, 256>>>();
    chunk_out_kernel<<<NBLK, 256>>>();
    o_gemm_kernel<<<grid, 256>>>(Wo, bo);
    gate_kernel<<<grid, 256>>>(x, Wg, bg, out);
}

// round 4
// speedup vs baseline: 1.4568x; 1.4568x over previous
#include <cuda_runtime.h>
#include <math.h>
#include <stdint.h>

#define BATCH 2
#define SEQ   1024
#define DIM   512
#define NH    8
#define HD    64
#define MROWS (BATCH*SEQ)      // 2048
#define CHK   32
#define NCHK  (SEQ/CHK)        // 32
#define NBH   (BATCH*NH)       // 16
#define NBLK  (NBH*NCHK)       // 512

// ---------------- scratch ---------------------------------------------------
__device__ float g_q  [MROWS*DIM];
__device__ float g_k  [MROWS*DIM];
__device__ float g_v  [MROWS*DIM];
__device__ float g_att[MROWS*DIM];
__device__ float g_o2 [MROWS*DIM];
__device__ float g_kv [NBLK*HD*HD];
__device__ float g_ks [NBLK*HD];

__device__ __forceinline__ float fmap(float t) {
    return t > 0.f ? t + 1.f : expf(t);
}

__device__ __forceinline__ uint32_t f2tf(float x) {
    uint32_t r;
    asm("cvt.rna.tf32.f32 %0, %1;" : "=r"(r) : "f"(x));
    return r;
}

__device__ __forceinline__ void mma_tf32(float c[4],
    uint32_t a0, uint32_t a1, uint32_t a2, uint32_t a3,
    uint32_t b0, uint32_t b1)
{
    asm volatile(
        "mma.sync.aligned.m16n8k8.row.col.f32.tf32.tf32.f32 "
        "{%0,%1,%2,%3},{%4,%5,%6,%7},{%8,%9},{%0,%1,%2,%3};"
        : "+f"(c[0]), "+f"(c[1]), "+f"(c[2]), "+f"(c[3])
        : "r"(a0), "r"(a1), "r"(a2), "r"(a3), "r"(b0), "r"(b1));
}

// ======================= tf32 GEMM framework ================================
// BM=128, BN=64, BK=16, 256 threads, 8 warps as 4(M)x2(N), warp tile 32x32.
// As[buf][128][20] (pad 20 words), Bs[buf][16][72] (pad 72 words), tf32 bits.

#define GEMM_SMEM \
    __shared__ uint32_t As[2][128][20]; \
    __shared__ uint32_t Bs[2][16][72];

#define GEMM_IDS \
    const int tid  = threadIdx.x; \
    const int lane = tid & 31, wid = tid >> 5; \
    const int g    = lane >> 2, tg = lane & 3; \
    const int warp_m = (wid >> 1) * 32, warp_n = (wid & 1) * 32; \
    const int row0 = blockIdx.y * 128, col0 = blockIdx.x * 64; \
    const int lr = tid >> 2, lk = (tid & 3) << 2; \
    const int bk = tid >> 4, bn = (tid & 15) << 2;

__device__ __forceinline__ void gemm_store_tiles(
    uint32_t (*Asb)[20], uint32_t (*Bsb)[72],
    int lr, int lk, int bk, int bn,
    float4 a0v, float4 a1v, float4 bv)
{
    *(uint4*)&Asb[lr][lk] =
        make_uint4(f2tf(a0v.x), f2tf(a0v.y), f2tf(a0v.z), f2tf(a0v.w));
    *(uint4*)&Asb[lr + 64][lk] =
        make_uint4(f2tf(a1v.x), f2tf(a1v.y), f2tf(a1v.z), f2tf(a1v.w));
    *(uint4*)&Bsb[bk][bn] =
        make_uint4(f2tf(bv.x), f2tf(bv.y), f2tf(bv.z), f2tf(bv.w));
}

__device__ __forceinline__ void gemm_compute(
    uint32_t (*Asb)[20], uint32_t (*Bsb)[72],
    int warp_m, int warp_n, int g, int tg, float acc[2][4][4])
{
#pragma unroll
    for (int ks = 0; ks < 2; ks++) {
        uint32_t af[2][4];
#pragma unroll
        for (int mt = 0; mt < 2; mt++) {
            int base = warp_m + mt * 16;
            af[mt][0] = Asb[base + g    ][ks * 8 + tg];
            af[mt][1] = Asb[base + g + 8][ks * 8 + tg];
            af[mt][2] = Asb[base + g    ][ks * 8 + tg + 4];
            af[mt][3] = Asb[base + g + 8][ks * 8 + tg + 4];
        }
        uint32_t bf[4][2];
#pragma unroll
        for (int nt = 0; nt < 4; nt++) {
            int col = warp_n + nt * 8 + g;
            bf[nt][0] = Bsb[ks * 8 + tg    ][col];
            bf[nt][1] = Bsb[ks * 8 + tg + 4][col];
        }
#pragma unroll
        for (int mt = 0; mt < 2; mt++)
#pragma unroll
            for (int nt = 0; nt < 4; nt++)
                mma_tf32(acc[mt][nt], af[mt][0], af[mt][1], af[mt][2], af[mt][3],
                         bf[nt][0], bf[nt][1]);
    }
}

// ---------------- fused QKV GEMM (tf32): z -> (Wq->g_q, Wk->g_k, Wv->g_v) ---
__global__ __launch_bounds__(256)
void qkv_gemm_kernel(const float* __restrict__ X,
                     const float* __restrict__ Wq,
                     const float* __restrict__ Wk,
                     const float* __restrict__ Wv)
{
    GEMM_SMEM; GEMM_IDS;
    const int z = blockIdx.z;
    const float* __restrict__ Bw = (z == 0) ? Wq : (z == 1) ? Wk : Wv;
    float* __restrict__ Cc       = (z == 0) ? g_q : (z == 1) ? g_k : g_v;

    float acc[2][4][4];
#pragma unroll
    for (int mt = 0; mt < 2; mt++)
#pragma unroll
        for (int nt = 0; nt < 4; nt++)
#pragma unroll
            for (int i = 0; i < 4; i++) acc[mt][nt][i] = 0.f;

    {   // first tile
        float4 a0v = *(const float4*)&X [(size_t)(row0 + lr)      * DIM + lk];
        float4 a1v = *(const float4*)&X [(size_t)(row0 + lr + 64) * DIM + lk];
        float4 bv  = *(const float4*)&Bw[(size_t)bk * DIM + col0 + bn];
        gemm_store_tiles(As[0], Bs[0], lr, lk, bk, bn, a0v, a1v, bv);
    }
    __syncthreads();

    int buf = 0;
    for (int k0 = 16; k0 < DIM; k0 += 16) {
        float4 a0v = *(const float4*)&X [(size_t)(row0 + lr)      * DIM + k0 + lk];
        float4 a1v = *(const float4*)&X [(size_t)(row0 + lr + 64) * DIM + k0 + lk];
        float4 bv  = *(const float4*)&Bw[(size_t)(k0 + bk) * DIM + col0 + bn];
        gemm_compute(As[buf], Bs[buf], warp_m, warp_n, g, tg, acc);
        gemm_store_tiles(As[buf ^ 1], Bs[buf ^ 1], lr, lk, bk, bn, a0v, a1v, bv);
        __syncthreads();
        buf ^= 1;
    }
    gemm_compute(As[buf], Bs[buf], warp_m, warp_n, g, tg, acc);

#pragma unroll
    for (int mt = 0; mt < 2; mt++) {
        int r0 = row0 + warp_m + mt * 16 + g;
#pragma unroll
        for (int nt = 0; nt < 4; nt++) {
            int c = col0 + warp_n + nt * 8 + tg * 2;
            float v0 = acc[mt][nt][0], v1 = acc[mt][nt][1];
            float v2 = acc[mt][nt][2], v3 = acc[mt][nt][3];
            if (z != 2) { v0 = fmap(v0); v1 = fmap(v1); v2 = fmap(v2); v3 = fmap(v3); }
            *(float2*)&Cc[(size_t)r0      * DIM + c] = make_float2(v0, v1);
            *(float2*)&Cc[(size_t)(r0 + 8) * DIM + c] = make_float2(v2, v3);
        }
    }
}

// ---------------- O GEMM (tf32): g_o2 = g_att @ Wo + bo ---------------------
__global__ __launch_bounds__(256)
void o_gemm_kernel(const float* __restrict__ Wo, const float* __restrict__ bias)
{
    GEMM_SMEM; GEMM_IDS;

    float acc[2][4][4];
#pragma unroll
    for (int mt = 0; mt < 2; mt++)
#pragma unroll
        for (int nt = 0; nt < 4; nt++)
#pragma unroll
            for (int i = 0; i < 4; i++) acc[mt][nt][i] = 0.f;

    {
        float4 a0v = *(const float4*)&g_att[(size_t)(row0 + lr)      * DIM + lk];
        float4 a1v = *(const float4*)&g_att[(size_t)(row0 + lr + 64) * DIM + lk];
        float4 bv  = *(const float4*)&Wo  [(size_t)bk * DIM + col0 + bn];
        gemm_store_tiles(As[0], Bs[0], lr, lk, bk, bn, a0v, a1v, bv);
    }
    __syncthreads();

    int buf = 0;
    for (int k0 = 16; k0 < DIM; k0 += 16) {
        float4 a0v = *(const float4*)&g_att[(size_t)(row0 + lr)      * DIM + k0 + lk];
        float4 a1v = *(const float4*)&g_att[(size_t)(row0 + lr + 64) * DIM + k0 + lk];
        float4 bv  = *(const float4*)&Wo  [(size_t)(k0 + bk) * DIM + col0 + bn];
        gemm_compute(As[buf], Bs[buf], warp_m, warp_n, g, tg, acc);
        gemm_store_tiles(As[buf ^ 1], Bs[buf ^ 1], lr, lk, bk, bn, a0v, a1v, bv);
        __syncthreads();
        buf ^= 1;
    }
    gemm_compute(As[buf], Bs[buf], warp_m, warp_n, g, tg, acc);

#pragma unroll
    for (int mt = 0; mt < 2; mt++) {
        int r0 = row0 + warp_m + mt * 16 + g;
#pragma unroll
        for (int nt = 0; nt < 4; nt++) {
            int c = col0 + warp_n + nt * 8 + tg * 2;
            float b0 = bias[c], b1 = bias[c + 1];
            *(float2*)&g_o2[(size_t)r0      * DIM + c] =
                make_float2(acc[mt][nt][0] + b0, acc[mt][nt][1] + b1);
            *(float2*)&g_o2[(size_t)(r0 + 8) * DIM + c] =
                make_float2(acc[mt][nt][2] + b0, acc[mt][nt][3] + b1);
        }
    }
}

// ---------------- gate GEMM (tf32): out = x + sig([x,o2]@Wg+bg)*(o2-x) ------
__global__ __launch_bounds__(256)
void gate_kernel(const float* __restrict__ X,
                 const float* __restrict__ Wg, const float* __restrict__ bg,
                 float* __restrict__ Out)
{
    GEMM_SMEM; GEMM_IDS;

    float acc[2][4][4];
#pragma unroll
    for (int mt = 0; mt < 2; mt++)
#pragma unroll
        for (int nt = 0; nt < 4; nt++)
#pragma unroll
            for (int i = 0; i < 4; i++) acc[mt][nt][i] = 0.f;

    {
        float4 a0v = *(const float4*)&X [(size_t)(row0 + lr)      * DIM + lk];
        float4 a1v = *(const float4*)&X [(size_t)(row0 + lr + 64) * DIM + lk];
        float4 bv  = *(const float4*)&Wg[(size_t)bk * DIM + col0 + bn];
        gemm_store_tiles(As[0], Bs[0], lr, lk, bk, bn, a0v, a1v, bv);
    }
    __syncthreads();

    int buf = 0;
    for (int k0 = 16; k0 < 2 * DIM; k0 += 16) {
        const float* __restrict__ src = (k0 < DIM) ? X : g_o2;
        int kb = k0 & (DIM - 1);
        float4 a0v = *(const float4*)&src[(size_t)(row0 + lr)      * DIM + kb + lk];
        float4 a1v = *(const float4*)&src[(size_t)(row0 + lr + 64) * DIM + kb + lk];
        float4 bv  = *(const float4*)&Wg [(size_t)(k0 + bk) * DIM + col0 + bn];
        gemm_compute(As[buf], Bs[buf], warp_m, warp_n, g, tg, acc);
        gemm_store_tiles(As[buf ^ 1], Bs[buf ^ 1], lr, lk, bk, bn, a0v, a1v, bv);
        __syncthreads();
        buf ^= 1;
    }
    gemm_compute(As[buf], Bs[buf], warp_m, warp_n, g, tg, acc);

#pragma unroll
    for (int mt = 0; mt < 2; mt++) {
        int r0 = row0 + warp_m + mt * 16 + g;
#pragma unroll
        for (int nt = 0; nt < 4; nt++) {
            int c = col0 + warp_n + nt * 8 + tg * 2;
            float b0 = bg[c], b1 = bg[c + 1];
#pragma unroll
            for (int half = 0; half < 2; half++) {
                int r = r0 + half * 8;
                float z0 = acc[mt][nt][half * 2]     + b0;
                float z1 = acc[mt][nt][half * 2 + 1] + b1;
                float g0 = 1.f / (1.f + expf(-z0));
                float g1 = 1.f / (1.f + expf(-z1));
                float2 xv = *(const float2*)&X   [(size_t)r * DIM + c];
                float2 ov = *(const float2*)&g_o2[(size_t)r * DIM + c];
                *(float2*)&Out[(size_t)r * DIM + c] =
                    make_float2(xv.x + g0 * (ov.x - xv.x),
                                xv.y + g1 * (ov.y - xv.y));
            }
        }
    }
}

// ---------------- phase A: per-chunk kv outer-product sums + k sums ---------
__global__ __launch_bounds__(256)
void chunk_sums_kernel()
{
    const int bid = blockIdx.x;
    const int c   = bid % NCHK;
    const int bh  = bid / NCHK;
    const int h   = bh % NH;
    const int b   = bh / NH;
    const int row0 = b * SEQ + c * CHK;
    const int col  = h * HD;

    __shared__ float ks[CHK][HD + 1];
    __shared__ float vs[CHK][HD + 1];
    for (int i = threadIdx.x; i < CHK * HD; i += 256) {
        int t = i / HD, d = i % HD;
        ks[t][d] = g_k[(size_t)(row0 + t) * DIM + col + d];
        vs[t][d] = g_v[(size_t)(row0 + t) * DIM + col + d];
    }
    __syncthreads();

    // each thread: one d, 16 consecutive e -> 16 independent accumulators
    const int d  = threadIdx.x >> 2;
    const int e0 = (threadIdx.x & 3) << 4;
    float acc[16];
#pragma unroll
    for (int j = 0; j < 16; j++) acc[j] = 0.f;
#pragma unroll
    for (int t = 0; t < CHK; t++) {
        float kv = ks[t][d];
#pragma unroll
        for (int j = 0; j < 16; j++) acc[j] += kv * vs[t][e0 + j];
    }
    const int base = bid * HD * HD + d * HD + e0;
#pragma unroll
    for (int j = 0; j < 16; j++) g_kv[base + j] = acc[j];

    if (threadIdx.x < HD) {
        float a = 0.f;
#pragma unroll
        for (int t = 0; t < CHK; t++) a += ks[t][threadIdx.x];
        g_ks[bid * HD + threadIdx.x] = a;
    }
}

// ---------------- phase B: exclusive prefix over chunks, in place -----------
__global__ __launch_bounds__(256)
void prefix_kernel()
{
    const int bh = blockIdx.x;              // 0..15
    // kv: 16 i's per thread, batched loads per chunk step (MLP 16)
    const int i0 = threadIdx.x;
    float run[16];
#pragma unroll
    for (int ii = 0; ii < 16; ii++) run[ii] = 0.f;
    for (int c = 0; c < NCHK; c++) {
        const int cbase = (bh * NCHK + c) * HD * HD;
#pragma unroll
        for (int ii = 0; ii < 16; ii++) {
            int idx = cbase + i0 + ii * 256;
            float t = g_kv[idx];
            g_kv[idx] = run[ii];
            run[ii] += t;
        }
    }
    // ks: threads 0..63, prefetch all 32 chunk values first
    if (threadIdx.x < HD) {
        float v[NCHK];
#pragma unroll
        for (int c = 0; c < NCHK; c++)
            v[c] = g_ks[(bh * NCHK + c) * HD + threadIdx.x];
        float r = 0.f;
#pragma unroll
        for (int c = 0; c < NCHK; c++) {
            g_ks[(bh * NCHK + c) * HD + threadIdx.x] = r;
            r += v[c];
        }
    }
}

// ---------------- phase C: intra-chunk causal attention ---------------------
__global__ __launch_bounds__(256)
void chunk_out_kernel()
{
    const int bid = blockIdx.x;
    const int c   = bid % NCHK;
    const int bh  = bid / NCHK;
    const int h   = bh % NH;
    const int b   = bh / NH;
    const int row0 = b * SEQ + c * CHK;
    const int col  = h * HD;

    __shared__ float qs[CHK][HD + 1];
    __shared__ float ks[CHK][HD + 1];
    __shared__ float vs[CHK][HD + 1];
    __shared__ float kvp[HD][HD + 1];
    __shared__ float Sc[CHK][CHK + 1];
    __shared__ float kp[HD];
    __shared__ float den[CHK];

    for (int i = threadIdx.x; i < CHK * HD; i += 256) {
        int t = i / HD, d = i % HD;
        qs[t][d] = g_q[(size_t)(row0 + t) * DIM + col + d];
        ks[t][d] = g_k[(size_t)(row0 + t) * DIM + col + d];
        vs[t][d] = g_v[(size_t)(row0 + t) * DIM + col + d];
    }
    const int base = bid * HD * HD;
    for (int i = threadIdx.x; i < HD * HD; i += 256)
        kvp[i / HD][i % HD] = g_kv[base + i];
    if (threadIdx.x < HD) kp[threadIdx.x] = g_ks[bid * HD + threadIdx.x];
    __syncthreads();

    // scores: each thread one s, 4 t's (ILP 4)
    {
        const int s  = threadIdx.x >> 3;
        const int t0 = (threadIdx.x & 7) << 2;
        float a[4] = {0.f, 0.f, 0.f, 0.f};
#pragma unroll 16
        for (int d = 0; d < HD; d++) {
            float qv = qs[s][d];
#pragma unroll
            for (int j = 0; j < 4; j++) a[j] += qv * ks[t0 + j][d];
        }
#pragma unroll
        for (int j = 0; j < 4; j++)
            Sc[s][t0 + j] = (t0 + j <= s) ? a[j] : 0.f;
    }
    __syncthreads();

    if (threadIdx.x < CHK) {
        const int s = threadIdx.x;
        float a = 0.f;
#pragma unroll 16
        for (int d = 0; d < HD; d++) a += qs[s][d] * kp[d];
#pragma unroll
        for (int t = 0; t < CHK; t++) a += Sc[s][t];
        den[s] = a + 1e-6f;
    }
    __syncthreads();

    // output: each thread one s, 8 e's (ILP 8)
    {
        const int s  = threadIdx.x >> 3;
        const int e0 = (threadIdx.x & 7) << 3;
        float a[8];
#pragma unroll
        for (int j = 0; j < 8; j++) a[j] = 0.f;
#pragma unroll 16
        for (int d = 0; d < HD; d++) {
            float qv = qs[s][d];
#pragma unroll
            for (int j = 0; j < 8; j++) a[j] += qv * kvp[d][e0 + j];
        }
#pragma unroll 8
        for (int t = 0; t < CHK; t++) {
            float sv = Sc[s][t];
#pragma unroll
            for (int j = 0; j < 8; j++) a[j] += sv * vs[t][e0 + j];
        }
        const float inv = 1.f / den[s];
        float* dst = &g_att[(size_t)(row0 + s) * DIM + col + e0];
#pragma unroll
        for (int j = 0; j < 8; j++) dst[j] = a[j] * inv;
    }
}

// ---------------- launcher --------------------------------------------------
extern "C" void kernel_launch(void* const* d_in, const int* in_sizes, int n_in,
                              void* d_out, int out_size)
{
    const float* x  = (const float*)d_in[0];
    const float* Wq = (const float*)d_in[1];
    const float* Wk = (const float*)d_in[2];
    const float* Wv = (const float*)d_in[3];
    const float* Wo = (const float*)d_in[4];
    const float* bo = (const float*)d_in[5];
    const float* Wg = (const float*)d_in[6];
    const float* bg = (const float*)d_in[7];
    float* out = (float*)d_out;

    dim3 grid (DIM / 64, MROWS / 128, 1);   // (8, 16)
    dim3 grid3(DIM / 64, MROWS / 128, 3);   // fused QKV

    qkv_gemm_kernel<<<grid3, 256>>>(x, Wq, Wk, Wv);
    chunk_sums_kernel<<<NBLK, 256>>>();
    prefix_kernel<<<NBH, 256>>>();
    chunk_out_kernel<<<NBLK, 256>>>();
    o_gemm_kernel<<<grid, 256>>>(Wo, bo);
    gate_kernel<<<grid, 256>>>(x, Wg, bg, out);
}

// round 5
// speedup vs baseline: 1.5566x; 1.0685x over previous
#include <cuda_runtime.h>
#include <math.h>
#include <stdint.h>

#define BATCH 2
#define SEQ   1024
#define DIM   512
#define NH    8
#define HD    64
#define MROWS (BATCH*SEQ)      // 2048
#define CHK   32
#define NCHK  (SEQ/CHK)        // 32
#define NBH   (BATCH*NH)       // 16
#define NBLK  (NBH*NCHK)       // 512

// ---------------- scratch ---------------------------------------------------
__device__ float g_q  [MROWS*DIM];
__device__ float g_k  [MROWS*DIM];
__device__ float g_v  [MROWS*DIM];
__device__ float g_att[MROWS*DIM];
__device__ float g_o2 [MROWS*DIM];
__device__ float g_kv [NBLK*HD*HD];
__device__ float g_ks [NBLK*HD];

__device__ __forceinline__ float fmap(float t) {
    return t > 0.f ? t + 1.f : expf(t);
}

__device__ __forceinline__ uint32_t f2tf(float x) {
    uint32_t r;
    asm("cvt.rna.tf32.f32 %0, %1;" : "=r"(r) : "f"(x));
    return r;
}

__device__ __forceinline__ void mma_tf32(float c[4],
    uint32_t a0, uint32_t a1, uint32_t a2, uint32_t a3,
    uint32_t b0, uint32_t b1)
{
    asm volatile(
        "mma.sync.aligned.m16n8k8.row.col.f32.tf32.tf32.f32 "
        "{%0,%1,%2,%3},{%4,%5,%6,%7},{%8,%9},{%0,%1,%2,%3};"
        : "+f"(c[0]), "+f"(c[1]), "+f"(c[2]), "+f"(c[3])
        : "r"(a0), "r"(a1), "r"(a2), "r"(a3), "r"(b0), "r"(b1));
}

// ======================= tf32 GEMM framework ================================
#define GEMM_SMEM \
    __shared__ uint32_t As[2][128][20]; \
    __shared__ uint32_t Bs[2][16][72];

#define GEMM_IDS \
    const int tid  = threadIdx.x; \
    const int lane = tid & 31, wid = tid >> 5; \
    const int g    = lane >> 2, tg = lane & 3; \
    const int warp_m = (wid >> 1) * 32, warp_n = (wid & 1) * 32; \
    const int row0 = blockIdx.y * 128, col0 = blockIdx.x * 64; \
    const int lr = tid >> 2, lk = (tid & 3) << 2; \
    const int bk = tid >> 4, bn = (tid & 15) << 2;

__device__ __forceinline__ void gemm_store_tiles(
    uint32_t (*Asb)[20], uint32_t (*Bsb)[72],
    int lr, int lk, int bk, int bn,
    float4 a0v, float4 a1v, float4 bv)
{
    *(uint4*)&Asb[lr][lk] =
        make_uint4(f2tf(a0v.x), f2tf(a0v.y), f2tf(a0v.z), f2tf(a0v.w));
    *(uint4*)&Asb[lr + 64][lk] =
        make_uint4(f2tf(a1v.x), f2tf(a1v.y), f2tf(a1v.z), f2tf(a1v.w));
    *(uint4*)&Bsb[bk][bn] =
        make_uint4(f2tf(bv.x), f2tf(bv.y), f2tf(bv.z), f2tf(bv.w));
}

__device__ __forceinline__ void gemm_compute(
    uint32_t (*Asb)[20], uint32_t (*Bsb)[72],
    int warp_m, int warp_n, int g, int tg, float acc[2][4][4])
{
#pragma unroll
    for (int ks = 0; ks < 2; ks++) {
        uint32_t af[2][4];
#pragma unroll
        for (int mt = 0; mt < 2; mt++) {
            int base = warp_m + mt * 16;
            af[mt][0] = Asb[base + g    ][ks * 8 + tg];
            af[mt][1] = Asb[base + g + 8][ks * 8 + tg];
            af[mt][2] = Asb[base + g    ][ks * 8 + tg + 4];
            af[mt][3] = Asb[base + g + 8][ks * 8 + tg + 4];
        }
        uint32_t bf[4][2];
#pragma unroll
        for (int nt = 0; nt < 4; nt++) {
            int col = warp_n + nt * 8 + g;
            bf[nt][0] = Bsb[ks * 8 + tg    ][col];
            bf[nt][1] = Bsb[ks * 8 + tg + 4][col];
        }
#pragma unroll
        for (int mt = 0; mt < 2; mt++)
#pragma unroll
            for (int nt = 0; nt < 4; nt++)
                mma_tf32(acc[mt][nt], af[mt][0], af[mt][1], af[mt][2], af[mt][3],
                         bf[nt][0], bf[nt][1]);
    }
}

// ---------------- fused QKV GEMM (tf32) -------------------------------------
__global__ __launch_bounds__(256)
void qkv_gemm_kernel(const float* __restrict__ X,
                     const float* __restrict__ Wq,
                     const float* __restrict__ Wk,
                     const float* __restrict__ Wv)
{
    GEMM_SMEM; GEMM_IDS;
    const int z = blockIdx.z;
    const float* __restrict__ Bw = (z == 0) ? Wq : (z == 1) ? Wk : Wv;
    float* __restrict__ Cc       = (z == 0) ? g_q : (z == 1) ? g_k : g_v;

    float acc[2][4][4];
#pragma unroll
    for (int mt = 0; mt < 2; mt++)
#pragma unroll
        for (int nt = 0; nt < 4; nt++)
#pragma unroll
            for (int i = 0; i < 4; i++) acc[mt][nt][i] = 0.f;

    {
        float4 a0v = *(const float4*)&X [(size_t)(row0 + lr)      * DIM + lk];
        float4 a1v = *(const float4*)&X [(size_t)(row0 + lr + 64) * DIM + lk];
        float4 bv  = *(const float4*)&Bw[(size_t)bk * DIM + col0 + bn];
        gemm_store_tiles(As[0], Bs[0], lr, lk, bk, bn, a0v, a1v, bv);
    }
    __syncthreads();

    int buf = 0;
    for (int k0 = 16; k0 < DIM; k0 += 16) {
        float4 a0v = *(const float4*)&X [(size_t)(row0 + lr)      * DIM + k0 + lk];
        float4 a1v = *(const float4*)&X [(size_t)(row0 + lr + 64) * DIM + k0 + lk];
        float4 bv  = *(const float4*)&Bw[(size_t)(k0 + bk) * DIM + col0 + bn];
        gemm_compute(As[buf], Bs[buf], warp_m, warp_n, g, tg, acc);
        gemm_store_tiles(As[buf ^ 1], Bs[buf ^ 1], lr, lk, bk, bn, a0v, a1v, bv);
        __syncthreads();
        buf ^= 1;
    }
    gemm_compute(As[buf], Bs[buf], warp_m, warp_n, g, tg, acc);

#pragma unroll
    for (int mt = 0; mt < 2; mt++) {
        int r0 = row0 + warp_m + mt * 16 + g;
#pragma unroll
        for (int nt = 0; nt < 4; nt++) {
            int c = col0 + warp_n + nt * 8 + tg * 2;
            float v0 = acc[mt][nt][0], v1 = acc[mt][nt][1];
            float v2 = acc[mt][nt][2], v3 = acc[mt][nt][3];
            if (z != 2) { v0 = fmap(v0); v1 = fmap(v1); v2 = fmap(v2); v3 = fmap(v3); }
            *(float2*)&Cc[(size_t)r0      * DIM + c] = make_float2(v0, v1);
            *(float2*)&Cc[(size_t)(r0 + 8) * DIM + c] = make_float2(v2, v3);
        }
    }
}

// ---------------- O GEMM (tf32) ---------------------------------------------
__global__ __launch_bounds__(256)
void o_gemm_kernel(const float* __restrict__ Wo, const float* __restrict__ bias)
{
    GEMM_SMEM; GEMM_IDS;

    float acc[2][4][4];
#pragma unroll
    for (int mt = 0; mt < 2; mt++)
#pragma unroll
        for (int nt = 0; nt < 4; nt++)
#pragma unroll
            for (int i = 0; i < 4; i++) acc[mt][nt][i] = 0.f;

    {
        float4 a0v = *(const float4*)&g_att[(size_t)(row0 + lr)      * DIM + lk];
        float4 a1v = *(const float4*)&g_att[(size_t)(row0 + lr + 64) * DIM + lk];
        float4 bv  = *(const float4*)&Wo  [(size_t)bk * DIM + col0 + bn];
        gemm_store_tiles(As[0], Bs[0], lr, lk, bk, bn, a0v, a1v, bv);
    }
    __syncthreads();

    int buf = 0;
    for (int k0 = 16; k0 < DIM; k0 += 16) {
        float4 a0v = *(const float4*)&g_att[(size_t)(row0 + lr)      * DIM + k0 + lk];
        float4 a1v = *(const float4*)&g_att[(size_t)(row0 + lr + 64) * DIM + k0 + lk];
        float4 bv  = *(const float4*)&Wo  [(size_t)(k0 + bk) * DIM + col0 + bn];
        gemm_compute(As[buf], Bs[buf], warp_m, warp_n, g, tg, acc);
        gemm_store_tiles(As[buf ^ 1], Bs[buf ^ 1], lr, lk, bk, bn, a0v, a1v, bv);
        __syncthreads();
        buf ^= 1;
    }
    gemm_compute(As[buf], Bs[buf], warp_m, warp_n, g, tg, acc);

#pragma unroll
    for (int mt = 0; mt < 2; mt++) {
        int r0 = row0 + warp_m + mt * 16 + g;
#pragma unroll
        for (int nt = 0; nt < 4; nt++) {
            int c = col0 + warp_n + nt * 8 + tg * 2;
            float b0 = bias[c], b1 = bias[c + 1];
            *(float2*)&g_o2[(size_t)r0      * DIM + c] =
                make_float2(acc[mt][nt][0] + b0, acc[mt][nt][1] + b1);
            *(float2*)&g_o2[(size_t)(r0 + 8) * DIM + c] =
                make_float2(acc[mt][nt][2] + b0, acc[mt][nt][3] + b1);
        }
    }
}

// ---------------- gate GEMM (tf32) ------------------------------------------
__global__ __launch_bounds__(256)
void gate_kernel(const float* __restrict__ X,
                 const float* __restrict__ Wg, const float* __restrict__ bg,
                 float* __restrict__ Out)
{
    GEMM_SMEM; GEMM_IDS;

    float acc[2][4][4];
#pragma unroll
    for (int mt = 0; mt < 2; mt++)
#pragma unroll
        for (int nt = 0; nt < 4; nt++)
#pragma unroll
            for (int i = 0; i < 4; i++) acc[mt][nt][i] = 0.f;

    {
        float4 a0v = *(const float4*)&X [(size_t)(row0 + lr)      * DIM + lk];
        float4 a1v = *(const float4*)&X [(size_t)(row0 + lr + 64) * DIM + lk];
        float4 bv  = *(const float4*)&Wg[(size_t)bk * DIM + col0 + bn];
        gemm_store_tiles(As[0], Bs[0], lr, lk, bk, bn, a0v, a1v, bv);
    }
    __syncthreads();

    int buf = 0;
    for (int k0 = 16; k0 < 2 * DIM; k0 += 16) {
        const float* __restrict__ src = (k0 < DIM) ? X : g_o2;
        int kb = k0 & (DIM - 1);
        float4 a0v = *(const float4*)&src[(size_t)(row0 + lr)      * DIM + kb + lk];
        float4 a1v = *(const float4*)&src[(size_t)(row0 + lr + 64) * DIM + kb + lk];
        float4 bv  = *(const float4*)&Wg [(size_t)(k0 + bk) * DIM + col0 + bn];
        gemm_compute(As[buf], Bs[buf], warp_m, warp_n, g, tg, acc);
        gemm_store_tiles(As[buf ^ 1], Bs[buf ^ 1], lr, lk, bk, bn, a0v, a1v, bv);
        __syncthreads();
        buf ^= 1;
    }
    gemm_compute(As[buf], Bs[buf], warp_m, warp_n, g, tg, acc);

#pragma unroll
    for (int mt = 0; mt < 2; mt++) {
        int r0 = row0 + warp_m + mt * 16 + g;
#pragma unroll
        for (int nt = 0; nt < 4; nt++) {
            int c = col0 + warp_n + nt * 8 + tg * 2;
            float b0 = bg[c], b1 = bg[c + 1];
#pragma unroll
            for (int half = 0; half < 2; half++) {
                int r = r0 + half * 8;
                float z0 = acc[mt][nt][half * 2]     + b0;
                float z1 = acc[mt][nt][half * 2 + 1] + b1;
                float g0 = 1.f / (1.f + expf(-z0));
                float g1 = 1.f / (1.f + expf(-z1));
                float2 xv = *(const float2*)&X   [(size_t)r * DIM + c];
                float2 ov = *(const float2*)&g_o2[(size_t)r * DIM + c];
                *(float2*)&Out[(size_t)r * DIM + c] =
                    make_float2(xv.x + g0 * (ov.x - xv.x),
                                xv.y + g1 * (ov.y - xv.y));
            }
        }
    }
}

// ---------------- phase A: per-chunk kv outer-product sums + k sums ---------
// vectorized: per t -> 1 broadcast LDS + 4 LDS.128 for 16 FFMA
__global__ __launch_bounds__(256)
void chunk_sums_kernel()
{
    const int bid = blockIdx.x;
    const int c   = bid % NCHK;
    const int bh  = bid / NCHK;
    const int h   = bh % NH;
    const int b   = bh / NH;
    const int row0 = b * SEQ + c * CHK;
    const int col  = h * HD;

    __shared__ float ks[CHK][HD + 4];
    __shared__ float vs[CHK][HD + 4];
    for (int i = threadIdx.x; i < CHK * (HD / 4); i += 256) {
        int t = i / (HD / 4), d4 = (i % (HD / 4)) * 4;
        *(float4*)&ks[t][d4] =
            *(const float4*)&g_k[(size_t)(row0 + t) * DIM + col + d4];
        *(float4*)&vs[t][d4] =
            *(const float4*)&g_v[(size_t)(row0 + t) * DIM + col + d4];
    }
    __syncthreads();

    const int d  = threadIdx.x >> 2;
    const int e0 = (threadIdx.x & 3) << 4;
    float acc[16];
#pragma unroll
    for (int j = 0; j < 16; j++) acc[j] = 0.f;
#pragma unroll
    for (int t = 0; t < CHK; t++) {
        float kv = ks[t][d];
#pragma unroll
        for (int j4 = 0; j4 < 4; j4++) {
            float4 vv = *(const float4*)&vs[t][e0 + j4 * 4];
            acc[j4*4+0] += kv * vv.x;
            acc[j4*4+1] += kv * vv.y;
            acc[j4*4+2] += kv * vv.z;
            acc[j4*4+3] += kv * vv.w;
        }
    }
    const int base = bid * HD * HD + d * HD + e0;
#pragma unroll
    for (int j4 = 0; j4 < 4; j4++)
        *(float4*)&g_kv[base + j4 * 4] =
            make_float4(acc[j4*4+0], acc[j4*4+1], acc[j4*4+2], acc[j4*4+3]);

    if (threadIdx.x < HD) {
        float a = 0.f;
#pragma unroll
        for (int t = 0; t < CHK; t++) a += ks[t][threadIdx.x];
        g_ks[bid * HD + threadIdx.x] = a;
    }
}

// ---------------- phase B: exclusive prefix over chunks, in place -----------
__global__ __launch_bounds__(256)
void prefix_kernel()
{
    const int bh = blockIdx.x;              // 0..15
    const int i0 = threadIdx.x;
    float run[16];
#pragma unroll
    for (int ii = 0; ii < 16; ii++) run[ii] = 0.f;
    for (int c = 0; c < NCHK; c++) {
        const int cbase = (bh * NCHK + c) * HD * HD;
#pragma unroll
        for (int ii = 0; ii < 16; ii++) {
            int idx = cbase + i0 + ii * 256;
            float t = g_kv[idx];
            g_kv[idx] = run[ii];
            run[ii] += t;
        }
    }
    if (threadIdx.x < HD) {
        float v[NCHK];
#pragma unroll
        for (int c = 0; c < NCHK; c++)
            v[c] = g_ks[(bh * NCHK + c) * HD + threadIdx.x];
        float r = 0.f;
#pragma unroll
        for (int c = 0; c < NCHK; c++) {
            g_ks[(bh * NCHK + c) * HD + threadIdx.x] = r;
            r += v[c];
        }
    }
}

// ---------------- phase C: intra-chunk causal attention (vectorized LDS) ----
__global__ __launch_bounds__(256)
void chunk_out_kernel()
{
    const int bid = blockIdx.x;
    const int c   = bid % NCHK;
    const int bh  = bid / NCHK;
    const int h   = bh % NH;
    const int b   = bh / NH;
    const int row0 = b * SEQ + c * CHK;
    const int col  = h * HD;

    __shared__ float qs [CHK][HD + 4];
    __shared__ float kst[HD][CHK + 4];    // k transposed: kst[d][t]
    __shared__ float vs [CHK][HD + 4];
    __shared__ float kvp[HD][HD + 4];
    __shared__ float Sc [CHK][CHK + 4];
    __shared__ float kp [HD];
    __shared__ float den[CHK];

    for (int i = threadIdx.x; i < CHK * (HD / 4); i += 256) {
        int t = i / (HD / 4), d4 = (i % (HD / 4)) * 4;
        *(float4*)&qs[t][d4] =
            *(const float4*)&g_q[(size_t)(row0 + t) * DIM + col + d4];
        float4 kv4 = *(const float4*)&g_k[(size_t)(row0 + t) * DIM + col + d4];
        kst[d4+0][t] = kv4.x; kst[d4+1][t] = kv4.y;
        kst[d4+2][t] = kv4.z; kst[d4+3][t] = kv4.w;
        *(float4*)&vs[t][d4] =
            *(const float4*)&g_v[(size_t)(row0 + t) * DIM + col + d4];
    }
    const int base = bid * HD * HD;
    for (int i = threadIdx.x; i < HD * (HD / 4); i += 256) {
        int d = i / (HD / 4), e4 = (i % (HD / 4)) * 4;
        *(float4*)&kvp[d][e4] = *(const float4*)&g_kv[base + d * HD + e4];
    }
    if (threadIdx.x < HD) kp[threadIdx.x] = g_ks[bid * HD + threadIdx.x];
    __syncthreads();

    // scores: each thread one s, 4 t's; per 4 d: 1 q float4 + 4 kst float4
    {
        const int s  = threadIdx.x >> 3;
        const int t0 = (threadIdx.x & 7) << 2;
        float a[4] = {0.f, 0.f, 0.f, 0.f};
#pragma unroll
        for (int d0 = 0; d0 < HD; d0 += 4) {
            float4 q4 = *(const float4*)&qs[s][d0];
            float4 kA = *(const float4*)&kst[d0+0][t0];
            float4 kB = *(const float4*)&kst[d0+1][t0];
            float4 kC = *(const float4*)&kst[d0+2][t0];
            float4 kD = *(const float4*)&kst[d0+3][t0];
            a[0] += q4.x*kA.x + q4.y*kB.x + q4.z*kC.x + q4.w*kD.x;
            a[1] += q4.x*kA.y + q4.y*kB.y + q4.z*kC.y + q4.w*kD.y;
            a[2] += q4.x*kA.z + q4.y*kB.z + q4.z*kC.z + q4.w*kD.z;
            a[3] += q4.x*kA.w + q4.y*kB.w + q4.z*kC.w + q4.w*kD.w;
        }
#pragma unroll
        for (int j = 0; j < 4; j++)
            Sc[s][t0 + j] = (t0 + j <= s) ? a[j] : 0.f;
    }
    __syncthreads();

    if (threadIdx.x < CHK) {
        const int s = threadIdx.x;
        float a = 0.f;
#pragma unroll
        for (int d0 = 0; d0 < HD; d0 += 4) {
            float4 q4 = *(const float4*)&qs[s][d0];
            float4 k4 = *(const float4*)&kp[d0];
            a += q4.x*k4.x + q4.y*k4.y + q4.z*k4.z + q4.w*k4.w;
        }
#pragma unroll
        for (int t0 = 0; t0 < CHK; t0 += 4) {
            float4 s4 = *(const float4*)&Sc[s][t0];
            a += s4.x + s4.y + s4.z + s4.w;
        }
        den[s] = a + 1e-6f;
    }
    __syncthreads();

    // output: each thread one s, 8 e's; vectorized kvp/vs/Sc reads
    {
        const int s  = threadIdx.x >> 3;
        const int e0 = (threadIdx.x & 7) << 3;
        float a[8];
#pragma unroll
        for (int j = 0; j < 8; j++) a[j] = 0.f;
#pragma unroll
        for (int d0 = 0; d0 < HD; d0 += 4) {
            float4 q4 = *(const float4*)&qs[s][d0];
            float qr[4] = {q4.x, q4.y, q4.z, q4.w};
#pragma unroll
            for (int dd = 0; dd < 4; dd++) {
                float4 vA = *(const float4*)&kvp[d0 + dd][e0];
                float4 vB = *(const float4*)&kvp[d0 + dd][e0 + 4];
                a[0] += qr[dd] * vA.x; a[1] += qr[dd] * vA.y;
                a[2] += qr[dd] * vA.z; a[3] += qr[dd] * vA.w;
                a[4] += qr[dd] * vB.x; a[5] += qr[dd] * vB.y;
                a[6] += qr[dd] * vB.z; a[7] += qr[dd] * vB.w;
            }
        }
#pragma unroll
        for (int t0 = 0; t0 < CHK; t0 += 4) {
            float4 s4 = *(const float4*)&Sc[s][t0];
            float sr[4] = {s4.x, s4.y, s4.z, s4.w};
#pragma unroll
            for (int tt = 0; tt < 4; tt++) {
                float4 vA = *(const float4*)&vs[t0 + tt][e0];
                float4 vB = *(const float4*)&vs[t0 + tt][e0 + 4];
                a[0] += sr[tt] * vA.x; a[1] += sr[tt] * vA.y;
                a[2] += sr[tt] * vA.z; a[3] += sr[tt] * vA.w;
                a[4] += sr[tt] * vB.x; a[5] += sr[tt] * vB.y;
                a[6] += sr[tt] * vB.z; a[7] += sr[tt] * vB.w;
            }
        }
        const float inv = 1.f / den[s];
        float* dst = &g_att[(size_t)(row0 + s) * DIM + col + e0];
        *(float4*)&dst[0] = make_float4(a[0]*inv, a[1]*inv, a[2]*inv, a[3]*inv);
        *(float4*)&dst[4] = make_float4(a[4]*inv, a[5]*inv, a[6]*inv, a[7]*inv);
    }
}

// ---------------- launcher --------------------------------------------------
extern "C" void kernel_launch(void* const* d_in, const int* in_sizes, int n_in,
                              void* d_out, int out_size)
{
    const float* x  = (const float*)d_in[0];
    const float* Wq = (const float*)d_in[1];
    const float* Wk = (const float*)d_in[2];
    const float* Wv = (const float*)d_in[3];
    const float* Wo = (const float*)d_in[4];
    const float* bo = (const float*)d_in[5];
    const float* Wg = (const float*)d_in[6];
    const float* bg = (const float*)d_in[7];
    float* out = (float*)d_out;

    dim3 grid (DIM / 64, MROWS / 128, 1);   // (8, 16)
    dim3 grid3(DIM / 64, MROWS / 128, 3);   // fused QKV

    qkv_gemm_kernel<<<grid3, 256>>>(x, Wq, Wk, Wv);
    chunk_sums_kernel<<<NBLK, 256>>>();
    prefix_kernel<<<NBH, 256>>>();
    chunk_out_kernel<<<NBLK, 256>>>();
    o_gemm_kernel<<<grid, 256>>>(Wo, bo);
    gate_kernel<<<grid, 256>>>(x, Wg, bg, out);
}

// round 6
// speedup vs baseline: 1.9186x; 1.2326x over previous
#include <cuda_runtime.h>
#include <math.h>
#include <stdint.h>

#define BATCH 2
#define SEQ   1024
#define DIM   512
#define NH    8
#define HD    64
#define MROWS (BATCH*SEQ)      // 2048
#define CHK   32
#define NCHK  (SEQ/CHK)        // 32
#define NBH   (BATCH*NH)       // 16
#define NBLK  (NBH*NCHK)       // 512

// ---------------- scratch ---------------------------------------------------
__device__ float g_q  [MROWS*DIM];
__device__ float g_k  [MROWS*DIM];
__device__ float g_v  [MROWS*DIM];
__device__ float g_att[MROWS*DIM];
__device__ float g_o2 [MROWS*DIM];
__device__ float g_kv [NBLK*HD*HD];
__device__ float g_ks [NBLK*HD];

__device__ __forceinline__ float fmap(float t) {
    return t > 0.f ? t + 1.f : expf(t);
}

__device__ __forceinline__ void mma_tf32(float c[4],
    uint32_t a0, uint32_t a1, uint32_t a2, uint32_t a3,
    uint32_t b0, uint32_t b1)
{
    asm volatile(
        "mma.sync.aligned.m16n8k8.row.col.f32.tf32.tf32.f32 "
        "{%0,%1,%2,%3},{%4,%5,%6,%7},{%8,%9},{%0,%1,%2,%3};"
        : "+f"(c[0]), "+f"(c[1]), "+f"(c[2]), "+f"(c[3])
        : "r"(a0), "r"(a1), "r"(a2), "r"(a3), "r"(b0), "r"(b1));
}

__device__ __forceinline__ void cp16(void* smem_dst, const void* gsrc) {
    uint32_t d = (uint32_t)__cvta_generic_to_shared(smem_dst);
    asm volatile("cp.async.ca.shared.global [%0], [%1], 16;" :: "r"(d), "l"(gsrc));
}
#define CP_COMMIT() asm volatile("cp.async.commit_group;")
#define CP_WAIT0()  asm volatile("cp.async.wait_group 0;")

// ======================= tf32 GEMM framework (cp.async, raw fp32->tf32) =====
// BM=128, BN=64, BK=16, 256 threads, 8 warps as 4(M)x2(N), warp tile 32x32.
#define GEMM_SMEM \
    __shared__ uint32_t As[2][128][20]; \
    __shared__ uint32_t Bs[2][16][72];

#define GEMM_IDS \
    const int tid  = threadIdx.x; \
    const int lane = tid & 31, wid = tid >> 5; \
    const int g    = lane >> 2, tg = lane & 3; \
    const int warp_m = (wid >> 1) * 32, warp_n = (wid & 1) * 32; \
    const int row0 = blockIdx.y * 128, col0 = blockIdx.x * 64; \
    const int lr = tid >> 2, lk = (tid & 3) << 2; \
    const int bk = tid >> 4, bn = (tid & 15) << 2;

__device__ __forceinline__ void gemm_copy_tile(
    uint32_t (*Asb)[20], uint32_t (*Bsb)[72],
    int lr, int lk, int bk, int bn,
    const float* aptr0, const float* aptr1, const float* bptr)
{
    cp16(&Asb[lr][lk],      aptr0);
    cp16(&Asb[lr + 64][lk], aptr1);
    cp16(&Bsb[bk][bn],      bptr);
    CP_COMMIT();
}

__device__ __forceinline__ void gemm_compute(
    uint32_t (*Asb)[20], uint32_t (*Bsb)[72],
    int warp_m, int warp_n, int g, int tg, float acc[2][4][4])
{
#pragma unroll
    for (int ks = 0; ks < 2; ks++) {
        uint32_t af[2][4];
#pragma unroll
        for (int mt = 0; mt < 2; mt++) {
            int base = warp_m + mt * 16;
            af[mt][0] = Asb[base + g    ][ks * 8 + tg];
            af[mt][1] = Asb[base + g + 8][ks * 8 + tg];
            af[mt][2] = Asb[base + g    ][ks * 8 + tg + 4];
            af[mt][3] = Asb[base + g + 8][ks * 8 + tg + 4];
        }
        uint32_t bf[4][2];
#pragma unroll
        for (int nt = 0; nt < 4; nt++) {
            int col = warp_n + nt * 8 + g;
            bf[nt][0] = Bsb[ks * 8 + tg    ][col];
            bf[nt][1] = Bsb[ks * 8 + tg + 4][col];
        }
#pragma unroll
        for (int mt = 0; mt < 2; mt++)
#pragma unroll
            for (int nt = 0; nt < 4; nt++)
                mma_tf32(acc[mt][nt], af[mt][0], af[mt][1], af[mt][2], af[mt][3],
                         bf[nt][0], bf[nt][1]);
    }
}

#define GEMM_ACC_INIT \
    float acc[2][4][4]; \
    _Pragma("unroll") \
    for (int mt = 0; mt < 2; mt++) \
        _Pragma("unroll") \
        for (int nt = 0; nt < 4; nt++) \
            _Pragma("unroll") \
            for (int i = 0; i < 4; i++) acc[mt][nt][i] = 0.f;

// ---------------- fused QKV GEMM --------------------------------------------
__global__ __launch_bounds__(256)
void qkv_gemm_kernel(const float* __restrict__ X,
                     const float* __restrict__ Wq,
                     const float* __restrict__ Wk,
                     const float* __restrict__ Wv)
{
    GEMM_SMEM; GEMM_IDS;
    const int z = blockIdx.z;
    const float* __restrict__ Bw = (z == 0) ? Wq : (z == 1) ? Wk : Wv;
    float* __restrict__ Cc       = (z == 0) ? g_q : (z == 1) ? g_k : g_v;

    GEMM_ACC_INIT;

    gemm_copy_tile(As[0], Bs[0], lr, lk, bk, bn,
                   &X[(size_t)(row0 + lr) * DIM + lk],
                   &X[(size_t)(row0 + lr + 64) * DIM + lk],
                   &Bw[(size_t)bk * DIM + col0 + bn]);
    int buf = 0;
    for (int k0 = 16; k0 < DIM; k0 += 16) {
        CP_WAIT0(); __syncthreads();
        gemm_copy_tile(As[buf ^ 1], Bs[buf ^ 1], lr, lk, bk, bn,
                       &X[(size_t)(row0 + lr) * DIM + k0 + lk],
                       &X[(size_t)(row0 + lr + 64) * DIM + k0 + lk],
                       &Bw[(size_t)(k0 + bk) * DIM + col0 + bn]);
        gemm_compute(As[buf], Bs[buf], warp_m, warp_n, g, tg, acc);
        buf ^= 1;
    }
    CP_WAIT0(); __syncthreads();
    gemm_compute(As[buf], Bs[buf], warp_m, warp_n, g, tg, acc);

#pragma unroll
    for (int mt = 0; mt < 2; mt++) {
        int r0 = row0 + warp_m + mt * 16 + g;
#pragma unroll
        for (int nt = 0; nt < 4; nt++) {
            int c = col0 + warp_n + nt * 8 + tg * 2;
            float v0 = acc[mt][nt][0], v1 = acc[mt][nt][1];
            float v2 = acc[mt][nt][2], v3 = acc[mt][nt][3];
            if (z != 2) { v0 = fmap(v0); v1 = fmap(v1); v2 = fmap(v2); v3 = fmap(v3); }
            *(float2*)&Cc[(size_t)r0      * DIM + c] = make_float2(v0, v1);
            *(float2*)&Cc[(size_t)(r0 + 8) * DIM + c] = make_float2(v2, v3);
        }
    }
}

// ---------------- O GEMM ----------------------------------------------------
__global__ __launch_bounds__(256)
void o_gemm_kernel(const float* __restrict__ Wo, const float* __restrict__ bias)
{
    GEMM_SMEM; GEMM_IDS;
    GEMM_ACC_INIT;

    gemm_copy_tile(As[0], Bs[0], lr, lk, bk, bn,
                   &g_att[(size_t)(row0 + lr) * DIM + lk],
                   &g_att[(size_t)(row0 + lr + 64) * DIM + lk],
                   &Wo[(size_t)bk * DIM + col0 + bn]);
    int buf = 0;
    for (int k0 = 16; k0 < DIM; k0 += 16) {
        CP_WAIT0(); __syncthreads();
        gemm_copy_tile(As[buf ^ 1], Bs[buf ^ 1], lr, lk, bk, bn,
                       &g_att[(size_t)(row0 + lr) * DIM + k0 + lk],
                       &g_att[(size_t)(row0 + lr + 64) * DIM + k0 + lk],
                       &Wo[(size_t)(k0 + bk) * DIM + col0 + bn]);
        gemm_compute(As[buf], Bs[buf], warp_m, warp_n, g, tg, acc);
        buf ^= 1;
    }
    CP_WAIT0(); __syncthreads();
    gemm_compute(As[buf], Bs[buf], warp_m, warp_n, g, tg, acc);

#pragma unroll
    for (int mt = 0; mt < 2; mt++) {
        int r0 = row0 + warp_m + mt * 16 + g;
#pragma unroll
        for (int nt = 0; nt < 4; nt++) {
            int c = col0 + warp_n + nt * 8 + tg * 2;
            float b0 = bias[c], b1 = bias[c + 1];
            *(float2*)&g_o2[(size_t)r0      * DIM + c] =
                make_float2(acc[mt][nt][0] + b0, acc[mt][nt][1] + b1);
            *(float2*)&g_o2[(size_t)(r0 + 8) * DIM + c] =
                make_float2(acc[mt][nt][2] + b0, acc[mt][nt][3] + b1);
        }
    }
}

// ---------------- gate GEMM -------------------------------------------------
__global__ __launch_bounds__(256)
void gate_kernel(const float* __restrict__ X,
                 const float* __restrict__ Wg, const float* __restrict__ bg,
                 float* __restrict__ Out)
{
    GEMM_SMEM; GEMM_IDS;
    GEMM_ACC_INIT;

    gemm_copy_tile(As[0], Bs[0], lr, lk, bk, bn,
                   &X[(size_t)(row0 + lr) * DIM + lk],
                   &X[(size_t)(row0 + lr + 64) * DIM + lk],
                   &Wg[(size_t)bk * DIM + col0 + bn]);
    int buf = 0;
    for (int k0 = 16; k0 < 2 * DIM; k0 += 16) {
        const float* __restrict__ src = (k0 < DIM) ? X : g_o2;
        int kb = k0 & (DIM - 1);
        CP_WAIT0(); __syncthreads();
        gemm_copy_tile(As[buf ^ 1], Bs[buf ^ 1], lr, lk, bk, bn,
                       &src[(size_t)(row0 + lr) * DIM + kb + lk],
                       &src[(size_t)(row0 + lr + 64) * DIM + kb + lk],
                       &Wg[(size_t)(k0 + bk) * DIM + col0 + bn]);
        gemm_compute(As[buf], Bs[buf], warp_m, warp_n, g, tg, acc);
        buf ^= 1;
    }
    CP_WAIT0(); __syncthreads();
    gemm_compute(As[buf], Bs[buf], warp_m, warp_n, g, tg, acc);

#pragma unroll
    for (int mt = 0; mt < 2; mt++) {
        int r0 = row0 + warp_m + mt * 16 + g;
#pragma unroll
        for (int nt = 0; nt < 4; nt++) {
            int c = col0 + warp_n + nt * 8 + tg * 2;
            float b0 = bg[c], b1 = bg[c + 1];
#pragma unroll
            for (int half = 0; half < 2; half++) {
                int r = r0 + half * 8;
                float z0 = acc[mt][nt][half * 2]     + b0;
                float z1 = acc[mt][nt][half * 2 + 1] + b1;
                float g0 = 1.f / (1.f + expf(-z0));
                float g1 = 1.f / (1.f + expf(-z1));
                float2 xv = *(const float2*)&X   [(size_t)r * DIM + c];
                float2 ov = *(const float2*)&g_o2[(size_t)r * DIM + c];
                *(float2*)&Out[(size_t)r * DIM + c] =
                    make_float2(xv.x + g0 * (ov.x - xv.x),
                                xv.y + g1 * (ov.y - xv.y));
            }
        }
    }
}

// ---------------- phase A: per-chunk kv sums (2d x 8e register tiles) -------
__global__ __launch_bounds__(256)
void chunk_sums_kernel()
{
    const int bid = blockIdx.x;
    const int c   = bid % NCHK;
    const int bh  = bid / NCHK;
    const int h   = bh % NH;
    const int b   = bh / NH;
    const int row0 = b * SEQ + c * CHK;
    const int col  = h * HD;

    __shared__ float ks[CHK][HD + 4];
    __shared__ float vs[CHK][HD + 4];
    for (int i = threadIdx.x; i < CHK * (HD / 4); i += 256) {
        int t = i / (HD / 4), d4 = (i % (HD / 4)) * 4;
        *(float4*)&ks[t][d4] =
            *(const float4*)&g_k[(size_t)(row0 + t) * DIM + col + d4];
        *(float4*)&vs[t][d4] =
            *(const float4*)&g_v[(size_t)(row0 + t) * DIM + col + d4];
    }
    __syncthreads();

    const int d0 = (threadIdx.x >> 3) * 2;      // 0,2,..,62
    const int e0 = (threadIdx.x & 7) * 8;       // 0,8,..,56
    float acc[2][8];
#pragma unroll
    for (int i = 0; i < 2; i++)
#pragma unroll
        for (int j = 0; j < 8; j++) acc[i][j] = 0.f;

#pragma unroll
    for (int t = 0; t < CHK; t++) {
        float k0 = ks[t][d0], k1 = ks[t][d0 + 1];
        float4 vA = *(const float4*)&vs[t][e0];
        float4 vB = *(const float4*)&vs[t][e0 + 4];
        acc[0][0] += k0 * vA.x; acc[0][1] += k0 * vA.y;
        acc[0][2] += k0 * vA.z; acc[0][3] += k0 * vA.w;
        acc[0][4] += k0 * vB.x; acc[0][5] += k0 * vB.y;
        acc[0][6] += k0 * vB.z; acc[0][7] += k0 * vB.w;
        acc[1][0] += k1 * vA.x; acc[1][1] += k1 * vA.y;
        acc[1][2] += k1 * vA.z; acc[1][3] += k1 * vA.w;
        acc[1][4] += k1 * vB.x; acc[1][5] += k1 * vB.y;
        acc[1][6] += k1 * vB.z; acc[1][7] += k1 * vB.w;
    }
    const int base = bid * HD * HD;
#pragma unroll
    for (int i = 0; i < 2; i++) {
        *(float4*)&g_kv[base + (d0 + i) * HD + e0] =
            make_float4(acc[i][0], acc[i][1], acc[i][2], acc[i][3]);
        *(float4*)&g_kv[base + (d0 + i) * HD + e0 + 4] =
            make_float4(acc[i][4], acc[i][5], acc[i][6], acc[i][7]);
    }

    if (threadIdx.x < HD) {
        float a = 0.f;
#pragma unroll
        for (int t = 0; t < CHK; t++) a += ks[t][threadIdx.x];
        g_ks[bid * HD + threadIdx.x] = a;
    }
}

// ---------------- phase B: exclusive prefix over chunks, in place -----------
__global__ __launch_bounds__(256)
void prefix_kernel()
{
    const int bh = blockIdx.x;              // 0..15
    const int i0 = threadIdx.x;
    float run[16];
#pragma unroll
    for (int ii = 0; ii < 16; ii++) run[ii] = 0.f;
    for (int c = 0; c < NCHK; c++) {
        const int cbase = (bh * NCHK + c) * HD * HD;
#pragma unroll
        for (int ii = 0; ii < 16; ii++) {
            int idx = cbase + i0 + ii * 256;
            float t = g_kv[idx];
            g_kv[idx] = run[ii];
            run[ii] += t;
        }
    }
    if (threadIdx.x < HD) {
        float v[NCHK];
#pragma unroll
        for (int c = 0; c < NCHK; c++)
            v[c] = g_ks[(bh * NCHK + c) * HD + threadIdx.x];
        float r = 0.f;
#pragma unroll
        for (int c = 0; c < NCHK; c++) {
            g_ks[(bh * NCHK + c) * HD + threadIdx.x] = r;
            r += v[c];
        }
    }
}

// ---------------- phase C: intra-chunk attention (128 thr, 2s x 8e tiles) ---
__global__ __launch_bounds__(128)
void chunk_out_kernel()
{
    const int bid = blockIdx.x;
    const int c   = bid % NCHK;
    const int bh  = bid / NCHK;
    const int h   = bh % NH;
    const int b   = bh / NH;
    const int row0 = b * SEQ + c * CHK;
    const int col  = h * HD;

    __shared__ float qs [CHK][HD + 4];
    __shared__ float kst[HD][CHK + 4];    // k transposed: kst[d][t]
    __shared__ float vs [CHK][HD + 4];
    __shared__ float kvp[HD][HD + 4];
    __shared__ float Sc [CHK][CHK + 4];
    __shared__ float kp [HD];
    __shared__ float den[CHK];

    const int tid = threadIdx.x;
    for (int i = tid; i < CHK * (HD / 4); i += 128) {
        int t = i / (HD / 4), d4 = (i % (HD / 4)) * 4;
        *(float4*)&qs[t][d4] =
            *(const float4*)&g_q[(size_t)(row0 + t) * DIM + col + d4];
        float4 kv4 = *(const float4*)&g_k[(size_t)(row0 + t) * DIM + col + d4];
        kst[d4+0][t] = kv4.x; kst[d4+1][t] = kv4.y;
        kst[d4+2][t] = kv4.z; kst[d4+3][t] = kv4.w;
        *(float4*)&vs[t][d4] =
            *(const float4*)&g_v[(size_t)(row0 + t) * DIM + col + d4];
    }
    const int base = bid * HD * HD;
    for (int i = tid; i < HD * (HD / 4); i += 128) {
        int d = i / (HD / 4), e4 = (i % (HD / 4)) * 4;
        *(float4*)&kvp[d][e4] = *(const float4*)&g_kv[base + d * HD + e4];
    }
    if (tid < HD) kp[tid] = g_ks[bid * HD + tid];
    __syncthreads();

    const int sg = tid >> 3;          // 0..15
    const int s0 = sg * 2;            // 0,2,..,30

    // scores: 2s x 4t per thread
    {
        const int t0 = (tid & 7) * 4;
        float a0[4] = {0.f, 0.f, 0.f, 0.f};
        float a1[4] = {0.f, 0.f, 0.f, 0.f};
#pragma unroll
        for (int d0 = 0; d0 < HD; d0 += 4) {
            float4 qA = *(const float4*)&qs[s0][d0];
            float4 qB = *(const float4*)&qs[s0 + 1][d0];
            float4 kA = *(const float4*)&kst[d0+0][t0];
            float4 kB = *(const float4*)&kst[d0+1][t0];
            float4 kC = *(const float4*)&kst[d0+2][t0];
            float4 kD = *(const float4*)&kst[d0+3][t0];
            a0[0] += qA.x*kA.x + qA.y*kB.x + qA.z*kC.x + qA.w*kD.x;
            a0[1] += qA.x*kA.y + qA.y*kB.y + qA.z*kC.y + qA.w*kD.y;
            a0[2] += qA.x*kA.z + qA.y*kB.z + qA.z*kC.z + qA.w*kD.z;
            a0[3] += qA.x*kA.w + qA.y*kB.w + qA.z*kC.w + qA.w*kD.w;
            a1[0] += qB.x*kA.x + qB.y*kB.x + qB.z*kC.x + qB.w*kD.x;
            a1[1] += qB.x*kA.y + qB.y*kB.y + qB.z*kC.y + qB.w*kD.y;
            a1[2] += qB.x*kA.z + qB.y*kB.z + qB.z*kC.z + qB.w*kD.z;
            a1[3] += qB.x*kA.w + qB.y*kB.w + qB.z*kC.w + qB.w*kD.w;
        }
#pragma unroll
        for (int j = 0; j < 4; j++) {
            Sc[s0    ][t0 + j] = (t0 + j <= s0    ) ? a0[j] : 0.f;
            Sc[s0 + 1][t0 + j] = (t0 + j <= s0 + 1) ? a1[j] : 0.f;
        }
    }
    __syncthreads();

    if (tid < CHK) {
        const int s = tid;
        float a = 0.f;
#pragma unroll
        for (int d0 = 0; d0 < HD; d0 += 4) {
            float4 q4 = *(const float4*)&qs[s][d0];
            float4 k4 = *(const float4*)&kp[d0];
            a += q4.x*k4.x + q4.y*k4.y + q4.z*k4.z + q4.w*k4.w;
        }
#pragma unroll
        for (int t0 = 0; t0 < CHK; t0 += 4) {
            float4 s4 = *(const float4*)&Sc[s][t0];
            a += s4.x + s4.y + s4.z + s4.w;
        }
        den[s] = a + 1e-6f;
    }
    __syncthreads();

    // output: 2s x 8e per thread
    {
        const int e0 = (tid & 7) * 8;
        float a0[8], a1[8];
#pragma unroll
        for (int j = 0; j < 8; j++) { a0[j] = 0.f; a1[j] = 0.f; }

#pragma unroll
        for (int d0 = 0; d0 < HD; d0 += 4) {
            float4 qA = *(const float4*)&qs[s0][d0];
            float4 qB = *(const float4*)&qs[s0 + 1][d0];
            float qa[4] = {qA.x, qA.y, qA.z, qA.w};
            float qb[4] = {qB.x, qB.y, qB.z, qB.w};
#pragma unroll
            for (int dd = 0; dd < 4; dd++) {
                float4 vA = *(const float4*)&kvp[d0 + dd][e0];
                float4 vB = *(const float4*)&kvp[d0 + dd][e0 + 4];
                a0[0] += qa[dd] * vA.x; a0[1] += qa[dd] * vA.y;
                a0[2] += qa[dd] * vA.z; a0[3] += qa[dd] * vA.w;
                a0[4] += qa[dd] * vB.x; a0[5] += qa[dd] * vB.y;
                a0[6] += qa[dd] * vB.z; a0[7] += qa[dd] * vB.w;
                a1[0] += qb[dd] * vA.x; a1[1] += qb[dd] * vA.y;
                a1[2] += qb[dd] * vA.z; a1[3] += qb[dd] * vA.w;
                a1[4] += qb[dd] * vB.x; a1[5] += qb[dd] * vB.y;
                a1[6] += qb[dd] * vB.z; a1[7] += qb[dd] * vB.w;
            }
        }
#pragma unroll
        for (int t0 = 0; t0 < CHK; t0 += 4) {
            float4 sA = *(const float4*)&Sc[s0][t0];
            float4 sB = *(const float4*)&Sc[s0 + 1][t0];
            float sa[4] = {sA.x, sA.y, sA.z, sA.w};
            float sb[4] = {sB.x, sB.y, sB.z, sB.w};
#pragma unroll
            for (int tt = 0; tt < 4; tt++) {
                float4 vA = *(const float4*)&vs[t0 + tt][e0];
                float4 vB = *(const float4*)&vs[t0 + tt][e0 + 4];
                a0[0] += sa[tt] * vA.x; a0[1] += sa[tt] * vA.y;
                a0[2] += sa[tt] * vA.z; a0[3] += sa[tt] * vA.w;
                a0[4] += sa[tt] * vB.x; a0[5] += sa[tt] * vB.y;
                a0[6] += sa[tt] * vB.z; a0[7] += sa[tt] * vB.w;
                a1[0] += sb[tt] * vA.x; a1[1] += sb[tt] * vA.y;
                a1[2] += sb[tt] * vA.z; a1[3] += sb[tt] * vA.w;
                a1[4] += sb[tt] * vB.x; a1[5] += sb[tt] * vB.y;
                a1[6] += sb[tt] * vB.z; a1[7] += sb[tt] * vB.w;
            }
        }
        const float inv0 = 1.f / den[s0];
        const float inv1 = 1.f / den[s0 + 1];
        float* d0p = &g_att[(size_t)(row0 + s0)     * DIM + col + e0];
        float* d1p = &g_att[(size_t)(row0 + s0 + 1) * DIM + col + e0];
        *(float4*)&d0p[0] = make_float4(a0[0]*inv0, a0[1]*inv0, a0[2]*inv0, a0[3]*inv0);
        *(float4*)&d0p[4] = make_float4(a0[4]*inv0, a0[5]*inv0, a0[6]*inv0, a0[7]*inv0);
        *(float4*)&d1p[0] = make_float4(a1[0]*inv1, a1[1]*inv1, a1[2]*inv1, a1[3]*inv1);
        *(float4*)&d1p[4] = make_float4(a1[4]*inv1, a1[5]*inv1, a1[6]*inv1, a1[7]*inv1);
    }
}

// ---------------- launcher --------------------------------------------------
extern "C" void kernel_launch(void* const* d_in, const int* in_sizes, int n_in,
                              void* d_out, int out_size)
{
    const float* x  = (const float*)d_in[0];
    const float* Wq = (const float*)d_in[1];
    const float* Wk = (const float*)d_in[2];
    const float* Wv = (const float*)d_in[3];
    const float* Wo = (const float*)d_in[4];
    const float* bo = (const float*)d_in[5];
    const float* Wg = (const float*)d_in[6];
    const float* bg = (const float*)d_in[7];
    float* out = (float*)d_out;

    dim3 grid (DIM / 64, MROWS / 128, 1);   // (8, 16)
    dim3 grid3(DIM / 64, MROWS / 128, 3);   // fused QKV

    qkv_gemm_kernel<<<grid3, 256>>>(x, Wq, Wk, Wv);
    chunk_sums_kernel<<<NBLK, 256>>>();
    prefix_kernel<<<NBH, 256>>>();
    chunk_out_kernel<<<NBLK, 128>>>();
    o_gemm_kernel<<<grid, 256>>>(Wo, bo);
    gate_kernel<<<grid, 256>>>(x, Wg, bg, out);
}

// round 8
// speedup vs baseline: 2.0581x; 1.0727x over previous
#include <cuda_runtime.h>
#include <math.h>
#include <stdint.h>

#define BATCH 2
#define SEQ   1024
#define DIM   512
#define NH    8
#define HD    64
#define MROWS (BATCH*SEQ)      // 2048
#define CHK   32
#define NCHK  (SEQ/CHK)        // 32
#define NBH   (BATCH*NH)       // 16
#define NBLK  (NBH*NCHK)       // 512

// ---------------- scratch ---------------------------------------------------
__device__ float g_q  [MROWS*DIM];
__device__ float g_k  [MROWS*DIM];
__device__ float g_v  [MROWS*DIM];
__device__ float g_att[MROWS*DIM];
__device__ float g_o2 [MROWS*DIM];
__device__ float g_kv [NBLK*HD*HD];
__device__ float g_ks [NBLK*HD];

__device__ __forceinline__ float fmap(float t) {
    return t > 0.f ? t + 1.f : expf(t);
}

__device__ __forceinline__ void mma_tf32(float c[4],
    uint32_t a0, uint32_t a1, uint32_t a2, uint32_t a3,
    uint32_t b0, uint32_t b1)
{
    asm volatile(
        "mma.sync.aligned.m16n8k8.row.col.f32.tf32.tf32.f32 "
        "{%0,%1,%2,%3},{%4,%5,%6,%7},{%8,%9},{%0,%1,%2,%3};"
        : "+f"(c[0]), "+f"(c[1]), "+f"(c[2]), "+f"(c[3])
        : "r"(a0), "r"(a1), "r"(a2), "r"(a3), "r"(b0), "r"(b1));
}

__device__ __forceinline__ void cp16(void* smem_dst, const void* gsrc) {
    uint32_t d = (uint32_t)__cvta_generic_to_shared(smem_dst);
    asm volatile("cp.async.cg.shared.global [%0], [%1], 16;" :: "r"(d), "l"(gsrc));
}
#define CP_COMMIT() asm volatile("cp.async.commit_group;")
#define CP_WAIT0()  asm volatile("cp.async.wait_group 0;")

// ======================= tf32 GEMM framework (BK=32, cp.async, dyn smem) ====
// BM=128, BN=64, BK=32, 256 threads, 8 warps as 4(M)x2(N), warp tile 32x32.
// 32 MMAs per warp between barriers (4 k-steps of 8).
#define AS_STRIDE 36
#define BS_STRIDE 72
#define AS_WORDS  (128 * AS_STRIDE)      // per buffer
#define BS_WORDS  (32 * BS_STRIDE)       // per buffer
#define GEMM_SMEM_BYTES ((2 * AS_WORDS + 2 * BS_WORDS) * 4)   // 55296

typedef uint32_t AsBuf[128][AS_STRIDE];
typedef uint32_t BsBuf[32][BS_STRIDE];

#define GEMM_SMEM \
    extern __shared__ uint32_t dynsmem[]; \
    AsBuf* As = (AsBuf*)dynsmem; \
    BsBuf* Bs = (BsBuf*)(dynsmem + 2 * AS_WORDS);

#define GEMM_IDS \
    const int tid  = threadIdx.x; \
    const int lane = tid & 31, wid = tid >> 5; \
    const int g    = lane >> 2, tg = lane & 3; \
    const int warp_m = (wid >> 1) * 32, warp_n = (wid & 1) * 32; \
    const int row0 = blockIdx.y * 128, col0 = blockIdx.x * 64;

// Ag = &A[row0*lda + k0], Bg = &B[k0*ldb + col0]
__device__ __forceinline__ void gemm_copy_tile(
    uint32_t (*Asb)[AS_STRIDE], uint32_t (*Bsb)[BS_STRIDE], int tid,
    const float* Ag, size_t lda, const float* Bg, size_t ldb)
{
    const int ar = tid >> 3;            // 0..31
    const int ac = (tid & 7) * 4;       // 0,4,..,28
#pragma unroll
    for (int p = 0; p < 4; p++)
        cp16(&Asb[ar + p * 32][ac], Ag + (size_t)(ar + p * 32) * lda + ac);
#pragma unroll
    for (int p = 0; p < 2; p++) {
        int idx = tid + p * 256;
        int br  = idx >> 4;             // 0..31
        int bc  = (idx & 15) * 4;       // 0,4,..,60
        cp16(&Bsb[br][bc], Bg + (size_t)br * ldb + bc);
    }
    CP_COMMIT();
}

__device__ __forceinline__ void gemm_compute(
    uint32_t (*Asb)[AS_STRIDE], uint32_t (*Bsb)[BS_STRIDE],
    int warp_m, int warp_n, int g, int tg, float acc[2][4][4])
{
#pragma unroll
    for (int ks = 0; ks < 4; ks++) {
        uint32_t af[2][4];
#pragma unroll
        for (int mt = 0; mt < 2; mt++) {
            int base = warp_m + mt * 16;
            af[mt][0] = Asb[base + g    ][ks * 8 + tg];
            af[mt][1] = Asb[base + g + 8][ks * 8 + tg];
            af[mt][2] = Asb[base + g    ][ks * 8 + tg + 4];
            af[mt][3] = Asb[base + g + 8][ks * 8 + tg + 4];
        }
        uint32_t bf[4][2];
#pragma unroll
        for (int nt = 0; nt < 4; nt++) {
            int col = warp_n + nt * 8 + g;
            bf[nt][0] = Bsb[ks * 8 + tg    ][col];
            bf[nt][1] = Bsb[ks * 8 + tg + 4][col];
        }
#pragma unroll
        for (int mt = 0; mt < 2; mt++)
#pragma unroll
            for (int nt = 0; nt < 4; nt++)
                mma_tf32(acc[mt][nt], af[mt][0], af[mt][1], af[mt][2], af[mt][3],
                         bf[nt][0], bf[nt][1]);
    }
}

#define GEMM_ACC_INIT \
    float acc[2][4][4]; \
    _Pragma("unroll") \
    for (int mt = 0; mt < 2; mt++) \
        _Pragma("unroll") \
        for (int nt = 0; nt < 4; nt++) \
            _Pragma("unroll") \
            for (int i = 0; i < 4; i++) acc[mt][nt][i] = 0.f;

// ---------------- fused QKV GEMM --------------------------------------------
__global__ __launch_bounds__(256)
void qkv_gemm_kernel(const float* __restrict__ X,
                     const float* __restrict__ Wq,
                     const float* __restrict__ Wk,
                     const float* __restrict__ Wv)
{
    GEMM_SMEM; GEMM_IDS;
    const int z = blockIdx.z;
    const float* __restrict__ Bw = (z == 0) ? Wq : (z == 1) ? Wk : Wv;
    float* __restrict__ Cc       = (z == 0) ? g_q : (z == 1) ? g_k : g_v;

    GEMM_ACC_INIT;

    gemm_copy_tile(As[0], Bs[0], tid,
                   &X[(size_t)row0 * DIM], DIM, &Bw[col0], DIM);
    int buf = 0;
    for (int k0 = 32; k0 < DIM; k0 += 32) {
        CP_WAIT0(); __syncthreads();
        gemm_copy_tile(As[buf ^ 1], Bs[buf ^ 1], tid,
                       &X[(size_t)row0 * DIM + k0], DIM,
                       &Bw[(size_t)k0 * DIM + col0], DIM);
        gemm_compute(As[buf], Bs[buf], warp_m, warp_n, g, tg, acc);
        buf ^= 1;
    }
    CP_WAIT0(); __syncthreads();
    gemm_compute(As[buf], Bs[buf], warp_m, warp_n, g, tg, acc);

#pragma unroll
    for (int mt = 0; mt < 2; mt++) {
        int r0 = row0 + warp_m + mt * 16 + g;
#pragma unroll
        for (int nt = 0; nt < 4; nt++) {
            int c = col0 + warp_n + nt * 8 + tg * 2;
            float v0 = acc[mt][nt][0], v1 = acc[mt][nt][1];
            float v2 = acc[mt][nt][2], v3 = acc[mt][nt][3];
            if (z != 2) { v0 = fmap(v0); v1 = fmap(v1); v2 = fmap(v2); v3 = fmap(v3); }
            *(float2*)&Cc[(size_t)r0      * DIM + c] = make_float2(v0, v1);
            *(float2*)&Cc[(size_t)(r0 + 8) * DIM + c] = make_float2(v2, v3);
        }
    }
}

// ---------------- O GEMM ----------------------------------------------------
__global__ __launch_bounds__(256)
void o_gemm_kernel(const float* __restrict__ Wo, const float* __restrict__ bias)
{
    GEMM_SMEM; GEMM_IDS;
    GEMM_ACC_INIT;

    gemm_copy_tile(As[0], Bs[0], tid,
                   &g_att[(size_t)row0 * DIM], DIM, &Wo[col0], DIM);
    int buf = 0;
    for (int k0 = 32; k0 < DIM; k0 += 32) {
        CP_WAIT0(); __syncthreads();
        gemm_copy_tile(As[buf ^ 1], Bs[buf ^ 1], tid,
                       &g_att[(size_t)row0 * DIM + k0], DIM,
                       &Wo[(size_t)k0 * DIM + col0], DIM);
        gemm_compute(As[buf], Bs[buf], warp_m, warp_n, g, tg, acc);
        buf ^= 1;
    }
    CP_WAIT0(); __syncthreads();
    gemm_compute(As[buf], Bs[buf], warp_m, warp_n, g, tg, acc);

#pragma unroll
    for (int mt = 0; mt < 2; mt++) {
        int r0 = row0 + warp_m + mt * 16 + g;
#pragma unroll
        for (int nt = 0; nt < 4; nt++) {
            int c = col0 + warp_n + nt * 8 + tg * 2;
            float b0 = bias[c], b1 = bias[c + 1];
            *(float2*)&g_o2[(size_t)r0      * DIM + c] =
                make_float2(acc[mt][nt][0] + b0, acc[mt][nt][1] + b1);
            *(float2*)&g_o2[(size_t)(r0 + 8) * DIM + c] =
                make_float2(acc[mt][nt][2] + b0, acc[mt][nt][3] + b1);
        }
    }
}

// ---------------- gate GEMM -------------------------------------------------
__global__ __launch_bounds__(256)
void gate_kernel(const float* __restrict__ X,
                 const float* __restrict__ Wg, const float* __restrict__ bg,
                 float* __restrict__ Out)
{
    GEMM_SMEM; GEMM_IDS;
    GEMM_ACC_INIT;

    gemm_copy_tile(As[0], Bs[0], tid,
                   &X[(size_t)row0 * DIM], DIM, &Wg[col0], DIM);
    int buf = 0;
    for (int k0 = 32; k0 < 2 * DIM; k0 += 32) {
        const float* __restrict__ src = (k0 < DIM) ? X : g_o2;
        int kb = k0 & (DIM - 1);
        CP_WAIT0(); __syncthreads();
        gemm_copy_tile(As[buf ^ 1], Bs[buf ^ 1], tid,
                       &src[(size_t)row0 * DIM + kb], DIM,
                       &Wg[(size_t)k0 * DIM + col0], DIM);
        gemm_compute(As[buf], Bs[buf], warp_m, warp_n, g, tg, acc);
        buf ^= 1;
    }
    CP_WAIT0(); __syncthreads();
    gemm_compute(As[buf], Bs[buf], warp_m, warp_n, g, tg, acc);

#pragma unroll
    for (int mt = 0; mt < 2; mt++) {
        int r0 = row0 + warp_m + mt * 16 + g;
#pragma unroll
        for (int nt = 0; nt < 4; nt++) {
            int c = col0 + warp_n + nt * 8 + tg * 2;
            float b0 = bg[c], b1 = bg[c + 1];
#pragma unroll
            for (int half = 0; half < 2; half++) {
                int r = r0 + half * 8;
                float z0 = acc[mt][nt][half * 2]     + b0;
                float z1 = acc[mt][nt][half * 2 + 1] + b1;
                float g0 = 1.f / (1.f + expf(-z0));
                float g1 = 1.f / (1.f + expf(-z1));
                float2 xv = *(const float2*)&X   [(size_t)r * DIM + c];
                float2 ov = *(const float2*)&g_o2[(size_t)r * DIM + c];
                *(float2*)&Out[(size_t)r * DIM + c] =
                    make_float2(xv.x + g0 * (ov.x - xv.x),
                                xv.y + g1 * (ov.y - xv.y));
            }
        }
    }
}

// ---------------- phase A: per-chunk kv sums (2d x 8e register tiles) -------
__global__ __launch_bounds__(256)
void chunk_sums_kernel()
{
    const int bid = blockIdx.x;
    const int c   = bid % NCHK;
    const int bh  = bid / NCHK;
    const int h   = bh % NH;
    const int b   = bh / NH;
    const int row0 = b * SEQ + c * CHK;
    const int col  = h * HD;

    __shared__ float ks[CHK][HD + 4];
    __shared__ float vs[CHK][HD + 4];
    for (int i = threadIdx.x; i < CHK * (HD / 4); i += 256) {
        int t = i / (HD / 4), d4 = (i % (HD / 4)) * 4;
        *(float4*)&ks[t][d4] =
            *(const float4*)&g_k[(size_t)(row0 + t) * DIM + col + d4];
        *(float4*)&vs[t][d4] =
            *(const float4*)&g_v[(size_t)(row0 + t) * DIM + col + d4];
    }
    __syncthreads();

    const int d0 = (threadIdx.x >> 3) * 2;      // 0,2,..,62
    const int e0 = (threadIdx.x & 7) * 8;       // 0,8,..,56
    float acc[2][8];
#pragma unroll
    for (int i = 0; i < 2; i++)
#pragma unroll
        for (int j = 0; j < 8; j++) acc[i][j] = 0.f;

#pragma unroll
    for (int t = 0; t < CHK; t++) {
        float k0 = ks[t][d0], k1 = ks[t][d0 + 1];
        float4 vA = *(const float4*)&vs[t][e0];
        float4 vB = *(const float4*)&vs[t][e0 + 4];
        acc[0][0] += k0 * vA.x; acc[0][1] += k0 * vA.y;
        acc[0][2] += k0 * vA.z; acc[0][3] += k0 * vA.w;
        acc[0][4] += k0 * vB.x; acc[0][5] += k0 * vB.y;
        acc[0][6] += k0 * vB.z; acc[0][7] += k0 * vB.w;
        acc[1][0] += k1 * vA.x; acc[1][1] += k1 * vA.y;
        acc[1][2] += k1 * vA.z; acc[1][3] += k1 * vA.w;
        acc[1][4] += k1 * vB.x; acc[1][5] += k1 * vB.y;
        acc[1][6] += k1 * vB.z; acc[1][7] += k1 * vB.w;
    }
    const int base = bid * HD * HD;
#pragma unroll
    for (int i = 0; i < 2; i++) {
        *(float4*)&g_kv[base + (d0 + i) * HD + e0] =
            make_float4(acc[i][0], acc[i][1], acc[i][2], acc[i][3]);
        *(float4*)&g_kv[base + (d0 + i) * HD + e0 + 4] =
            make_float4(acc[i][4], acc[i][5], acc[i][6], acc[i][7]);
    }

    if (threadIdx.x < HD) {
        float a = 0.f;
#pragma unroll
        for (int t = 0; t < CHK; t++) a += ks[t][threadIdx.x];
        g_ks[bid * HD + threadIdx.x] = a;
    }
}

// ---------------- phase B: exclusive prefix over chunks, in place -----------
__global__ __launch_bounds__(256)
void prefix_kernel()
{
    const int bh = blockIdx.x;              // 0..15
    const int i0 = threadIdx.x;
    float run[16];
#pragma unroll
    for (int ii = 0; ii < 16; ii++) run[ii] = 0.f;
    for (int c = 0; c < NCHK; c++) {
        const int cbase = (bh * NCHK + c) * HD * HD;
#pragma unroll
        for (int ii = 0; ii < 16; ii++) {
            int idx = cbase + i0 + ii * 256;
            float t = g_kv[idx];
            g_kv[idx] = run[ii];
            run[ii] += t;
        }
    }
    if (threadIdx.x < HD) {
        float v[NCHK];
#pragma unroll
        for (int c = 0; c < NCHK; c++)
            v[c] = g_ks[(bh * NCHK + c) * HD + threadIdx.x];
        float r = 0.f;
#pragma unroll
        for (int c = 0; c < NCHK; c++) {
            g_ks[(bh * NCHK + c) * HD + threadIdx.x] = r;
            r += v[c];
        }
    }
}

// ---------------- phase C: intra-chunk attention (128 thr, 2s x 8e tiles) ---
__global__ __launch_bounds__(128)
void chunk_out_kernel()
{
    const int bid = blockIdx.x;
    const int c   = bid % NCHK;
    const int bh  = bid / NCHK;
    const int h   = bh % NH;
    const int b   = bh / NH;
    const int row0 = b * SEQ + c * CHK;
    const int col  = h * HD;

    __shared__ float qs [CHK][HD + 4];
    __shared__ float kst[HD][CHK + 4];    // k transposed: kst[d][t]
    __shared__ float vs [CHK][HD + 4];
    __shared__ float kvp[HD][HD + 4];
    __shared__ float Sc [CHK][CHK + 4];
    __shared__ float kp [HD];
    __shared__ float den[CHK];

    const int tid = threadIdx.x;
    for (int i = tid; i < CHK * (HD / 4); i += 128) {
        int t = i / (HD / 4), d4 = (i % (HD / 4)) * 4;
        *(float4*)&qs[t][d4] =
            *(const float4*)&g_q[(size_t)(row0 + t) * DIM + col + d4];
        float4 kv4 = *(const float4*)&g_k[(size_t)(row0 + t) * DIM + col + d4];
        kst[d4+0][t] = kv4.x; kst[d4+1][t] = kv4.y;
        kst[d4+2][t] = kv4.z; kst[d4+3][t] = kv4.w;
        *(float4*)&vs[t][d4] =
            *(const float4*)&g_v[(size_t)(row0 + t) * DIM + col + d4];
    }
    const int base = bid * HD * HD;
    for (int i = tid; i < HD * (HD / 4); i += 128) {
        int d = i / (HD / 4), e4 = (i % (HD / 4)) * 4;
        *(float4*)&kvp[d][e4] = *(const float4*)&g_kv[base + d * HD + e4];
    }
    if (tid < HD) kp[tid] = g_ks[bid * HD + tid];
    __syncthreads();

    const int sg = tid >> 3;          // 0..15
    const int s0 = sg * 2;            // 0,2,..,30

    // scores: 2s x 4t per thread
    {
        const int t0 = (tid & 7) * 4;
        float a0[4] = {0.f, 0.f, 0.f, 0.f};
        float a1[4] = {0.f, 0.f, 0.f, 0.f};
#pragma unroll
        for (int d0 = 0; d0 < HD; d0 += 4) {
            float4 qA = *(const float4*)&qs[s0][d0];
            float4 qB = *(const float4*)&qs[s0 + 1][d0];
            float4 kA = *(const float4*)&kst[d0+0][t0];
            float4 kB = *(const float4*)&kst[d0+1][t0];
            float4 kC = *(const float4*)&kst[d0+2][t0];
            float4 kD = *(const float4*)&kst[d0+3][t0];
            a0[0] += qA.x*kA.x + qA.y*kB.x + qA.z*kC.x + qA.w*kD.x;
            a0[1] += qA.x*kA.y + qA.y*kB.y + qA.z*kC.y + qA.w*kD.y;
            a0[2] += qA.x*kA.z + qA.y*kB.z + qA.z*kC.z + qA.w*kD.z;
            a0[3] += qA.x*kA.w + qA.y*kB.w + qA.z*kC.w + qA.w*kD.w;
            a1[0] += qB.x*kA.x + qB.y*kB.x + qB.z*kC.x + qB.w*kD.x;
            a1[1] += qB.x*kA.y + qB.y*kB.y + qB.z*kC.y + qB.w*kD.y;
            a1[2] += qB.x*kA.z + qB.y*kB.z + qB.z*kC.z + qB.w*kD.z;
            a1[3] += qB.x*kA.w + qB.y*kB.w + qB.z*kC.w + qB.w*kD.w;
        }
#pragma unroll
        for (int j = 0; j < 4; j++) {
            Sc[s0    ][t0 + j] = (t0 + j <= s0    ) ? a0[j] : 0.f;
            Sc[s0 + 1][t0 + j] = (t0 + j <= s0 + 1) ? a1[j] : 0.f;
        }
    }
    __syncthreads();

    if (tid < CHK) {
        const int s = tid;
        float a = 0.f;
#pragma unroll
        for (int d0 = 0; d0 < HD; d0 += 4) {
            float4 q4 = *(const float4*)&qs[s][d0];
            float4 k4 = *(const float4*)&kp[d0];
            a += q4.x*k4.x + q4.y*k4.y + q4.z*k4.z + q4.w*k4.w;
        }
#pragma unroll
        for (int t0 = 0; t0 < CHK; t0 += 4) {
            float4 s4 = *(const float4*)&Sc[s][t0];
            a += s4.x + s4.y + s4.z + s4.w;
        }
        den[s] = a + 1e-6f;
    }
    __syncthreads();

    // output: 2s x 8e per thread
    {
        const int e0 = (tid & 7) * 8;
        float a0[8], a1[8];
#pragma unroll
        for (int j = 0; j < 8; j++) { a0[j] = 0.f; a1[j] = 0.f; }

#pragma unroll
        for (int d0 = 0; d0 < HD; d0 += 4) {
            float4 qA = *(const float4*)&qs[s0][d0];
            float4 qB = *(const float4*)&qs[s0 + 1][d0];
            float qa[4] = {qA.x, qA.y, qA.z, qA.w};
            float qb[4] = {qB.x, qB.y, qB.z, qB.w};
#pragma unroll
            for (int dd = 0; dd < 4; dd++) {
                float4 vA = *(const float4*)&kvp[d0 + dd][e0];
                float4 vB = *(const float4*)&kvp[d0 + dd][e0 + 4];
                a0[0] += qa[dd] * vA.x; a0[1] += qa[dd] * vA.y;
                a0[2] += qa[dd] * vA.z; a0[3] += qa[dd] * vA.w;
                a0[4] += qa[dd] * vB.x; a0[5] += qa[dd] * vB.y;
                a0[6] += qa[dd] * vB.z; a0[7] += qa[dd] * vB.w;
                a1[0] += qb[dd] * vA.x; a1[1] += qb[dd] * vA.y;
                a1[2] += qb[dd] * vA.z; a1[3] += qb[dd] * vA.w;
                a1[4] += qb[dd] * vB.x; a1[5] += qb[dd] * vB.y;
                a1[6] += qb[dd] * vB.z; a1[7] += qb[dd] * vB.w;
            }
        }
#pragma unroll
        for (int t0 = 0; t0 < CHK; t0 += 4) {
            float4 sA = *(const float4*)&Sc[s0][t0];
            float4 sB = *(const float4*)&Sc[s0 + 1][t0];
            float sa[4] = {sA.x, sA.y, sA.z, sA.w};
            float sb[4] = {sB.x, sB.y, sB.z, sB.w};
#pragma unroll
            for (int tt = 0; tt < 4; tt++) {
                float4 vA = *(const float4*)&vs[t0 + tt][e0];
                float4 vB = *(const float4*)&vs[t0 + tt][e0 + 4];
                a0[0] += sa[tt] * vA.x; a0[1] += sa[tt] * vA.y;
                a0[2] += sa[tt] * vA.z; a0[3] += sa[tt] * vA.w;
                a0[4] += sa[tt] * vB.x; a0[5] += sa[tt] * vB.y;
                a0[6] += sa[tt] * vB.z; a0[7] += sa[tt] * vB.w;
                a1[0] += sb[tt] * vA.x; a1[1] += sb[tt] * vA.y;
                a1[2] += sb[tt] * vA.z; a1[3] += sb[tt] * vA.w;
                a1[4] += sb[tt] * vB.x; a1[5] += sb[tt] * vB.y;
                a1[6] += sb[tt] * vB.z; a1[7] += sb[tt] * vB.w;
            }
        }
        const float inv0 = 1.f / den[s0];
        const float inv1 = 1.f / den[s0 + 1];
        float* d0p = &g_att[(size_t)(row0 + s0)     * DIM + col + e0];
        float* d1p = &g_att[(size_t)(row0 + s0 + 1) * DIM + col + e0];
        *(float4*)&d0p[0] = make_float4(a0[0]*inv0, a0[1]*inv0, a0[2]*inv0, a0[3]*inv0);
        *(float4*)&d0p[4] = make_float4(a0[4]*inv0, a0[5]*inv0, a0[6]*inv0, a0[7]*inv0);
        *(float4*)&d1p[0] = make_float4(a1[0]*inv1, a1[1]*inv1, a1[2]*inv1, a1[3]*inv1);
        *(float4*)&d1p[4] = make_float4(a1[4]*inv1, a1[5]*inv1, a1[6]*inv1, a1[7]*inv1);
    }
}

// ---------------- launcher --------------------------------------------------
extern "C" void kernel_launch(void* const* d_in, const int* in_sizes, int n_in,
                              void* d_out, int out_size)
{
    const float* x  = (const float*)d_in[0];
    const float* Wq = (const float*)d_in[1];
    const float* Wk = (const float*)d_in[2];
    const float* Wv = (const float*)d_in[3];
    const float* Wo = (const float*)d_in[4];
    const float* bo = (const float*)d_in[5];
    const float* Wg = (const float*)d_in[6];
    const float* bg = (const float*)d_in[7];
    float* out = (float*)d_out;

    // allow >48KB dynamic smem on the GEMM kernels (persistent attribute,
    // not an allocation, not a stream op)
    cudaFuncSetAttribute(qkv_gemm_kernel,
        cudaFuncAttributeMaxDynamicSharedMemorySize, GEMM_SMEM_BYTES);
    cudaFuncSetAttribute(o_gemm_kernel,
        cudaFuncAttributeMaxDynamicSharedMemorySize, GEMM_SMEM_BYTES);
    cudaFuncSetAttribute(gate_kernel,
        cudaFuncAttributeMaxDynamicSharedMemorySize, GEMM_SMEM_BYTES);

    dim3 grid (DIM / 64, MROWS / 128, 1);   // (8, 16)
    dim3 grid3(DIM / 64, MROWS / 128, 3);   // fused QKV

    qkv_gemm_kernel<<<grid3, 256, GEMM_SMEM_BYTES>>>(x, Wq, Wk, Wv);
    chunk_sums_kernel<<<NBLK, 256>>>();
    prefix_kernel<<<NBH, 256>>>();
    chunk_out_kernel<<<NBLK, 128>>>();
    o_gemm_kernel<<<grid, 256, GEMM_SMEM_BYTES>>>(Wo, bo);
    gate_kernel<<<grid, 256, GEMM_SMEM_BYTES>>>(x, Wg, bg, out);
}

// round 9
// speedup vs baseline: 2.8258x; 1.3730x over previous
#include <cuda_runtime.h>
#include <math.h>
#include <stdint.h>

#define BATCH 2
#define SEQ   1024
#define DIM   512
#define NH    8
#define HD    64
#define MROWS (BATCH*SEQ)      // 2048
#define CHK   32
#define NCHK  (SEQ/CHK)        // 32
#define NBH   (BATCH*NH)       // 16
#define NBLK  (NBH*NCHK)       // 512

// ---------------- scratch ---------------------------------------------------
__device__ float g_q  [MROWS*DIM];
__device__ float g_k  [MROWS*DIM];
__device__ float g_v  [MROWS*DIM];
__device__ float g_att[MROWS*DIM];
__device__ float g_o2 [MROWS*DIM];
__device__ float g_g1 [MROWS*DIM];   // x @ Wg[:512]  (precomputed with QKV)
__device__ float g_kv [NBLK*HD*HD];
__device__ float g_ks [NBLK*HD];

__device__ __forceinline__ float fmap(float t) {
    return t > 0.f ? t + 1.f : expf(t);
}

__device__ __forceinline__ void mma_tf32(float c[4],
    uint32_t a0, uint32_t a1, uint32_t a2, uint32_t a3,
    uint32_t b0, uint32_t b1)
{
    asm volatile(
        "mma.sync.aligned.m16n8k8.row.col.f32.tf32.tf32.f32 "
        "{%0,%1,%2,%3},{%4,%5,%6,%7},{%8,%9},{%0,%1,%2,%3};"
        : "+f"(c[0]), "+f"(c[1]), "+f"(c[2]), "+f"(c[3])
        : "r"(a0), "r"(a1), "r"(a2), "r"(a3), "r"(b0), "r"(b1));
}

__device__ __forceinline__ void cp16(void* smem_dst, const void* gsrc) {
    uint32_t d = (uint32_t)__cvta_generic_to_shared(smem_dst);
    asm volatile("cp.async.cg.shared.global [%0], [%1], 16;" :: "r"(d), "l"(gsrc));
}
#define CP_COMMIT() asm volatile("cp.async.commit_group;")
#define CP_WAIT0()  asm volatile("cp.async.wait_group 0;")

// ======================= tf32 GEMM framework ================================
// BM=128, BN=64, BK=32, 128 threads, 4 warps as 2(M)x2(N), warp tile 64x32.
// Per ks: 16+8=24 LDS for 16 MMAs (192 B/MMA vs 256 B/MMA at 32x32 tile).
#define AS_STRIDE 36
#define BS_STRIDE 72
#define AS_WORDS  (128 * AS_STRIDE)
#define BS_WORDS  (32 * BS_STRIDE)
#define GEMM_SMEM_BYTES ((2 * AS_WORDS + 2 * BS_WORDS) * 4)   // 55296

typedef uint32_t AsBuf[128][AS_STRIDE];
typedef uint32_t BsBuf[32][BS_STRIDE];

#define GEMM_SMEM \
    extern __shared__ uint32_t dynsmem[]; \
    AsBuf* As = (AsBuf*)dynsmem; \
    BsBuf* Bs = (BsBuf*)(dynsmem + 2 * AS_WORDS);

#define GEMM_IDS \
    const int tid  = threadIdx.x; \
    const int lane = tid & 31, wid = tid >> 5; \
    const int g    = lane >> 2, tg = lane & 3; \
    const int warp_m = (wid >> 1) * 64, warp_n = (wid & 1) * 32; \
    const int row0 = blockIdx.y * 128, col0 = blockIdx.x * 64;

// 128 threads: A tile 128x32 floats (8 cp16/thread), B tile 32x64 (4 cp16/thread)
__device__ __forceinline__ void gemm_copy_tile(
    uint32_t (*Asb)[AS_STRIDE], uint32_t (*Bsb)[BS_STRIDE], int tid,
    const float* Ag, size_t lda, const float* Bg, size_t ldb)
{
    const int ar = tid >> 3;            // 0..15
    const int ac = (tid & 7) * 4;       // 0,4,..,28
#pragma unroll
    for (int p = 0; p < 8; p++)
        cp16(&Asb[ar + p * 16][ac], Ag + (size_t)(ar + p * 16) * lda + ac);
#pragma unroll
    for (int p = 0; p < 4; p++) {
        int idx = tid + p * 128;
        int br  = idx >> 4;             // 0..31
        int bc  = (idx & 15) * 4;       // 0,4,..,60
        cp16(&Bsb[br][bc], Bg + (size_t)br * ldb + bc);
    }
    CP_COMMIT();
}

__device__ __forceinline__ void gemm_compute(
    uint32_t (*Asb)[AS_STRIDE], uint32_t (*Bsb)[BS_STRIDE],
    int warp_m, int warp_n, int g, int tg, float acc[4][4][4])
{
#pragma unroll
    for (int ks = 0; ks < 4; ks++) {
        uint32_t af[4][4];
#pragma unroll
        for (int mt = 0; mt < 4; mt++) {
            int base = warp_m + mt * 16;
            af[mt][0] = Asb[base + g    ][ks * 8 + tg];
            af[mt][1] = Asb[base + g + 8][ks * 8 + tg];
            af[mt][2] = Asb[base + g    ][ks * 8 + tg + 4];
            af[mt][3] = Asb[base + g + 8][ks * 8 + tg + 4];
        }
        uint32_t bf[4][2];
#pragma unroll
        for (int nt = 0; nt < 4; nt++) {
            int col = warp_n + nt * 8 + g;
            bf[nt][0] = Bsb[ks * 8 + tg    ][col];
            bf[nt][1] = Bsb[ks * 8 + tg + 4][col];
        }
#pragma unroll
        for (int mt = 0; mt < 4; mt++)
#pragma unroll
            for (int nt = 0; nt < 4; nt++)
                mma_tf32(acc[mt][nt], af[mt][0], af[mt][1], af[mt][2], af[mt][3],
                         bf[nt][0], bf[nt][1]);
    }
}

#define GEMM_ACC_INIT \
    float acc[4][4][4]; \
    _Pragma("unroll") \
    for (int mt = 0; mt < 4; mt++) \
        _Pragma("unroll") \
        for (int nt = 0; nt < 4; nt++) \
            _Pragma("unroll") \
            for (int i = 0; i < 4; i++) acc[mt][nt][i] = 0.f;

// ---------------- fused QKV+G1 GEMM (z: 0=q,1=k,2=v,3=g1) -------------------
__global__ __launch_bounds__(128)
void qkv_gemm_kernel(const float* __restrict__ X,
                     const float* __restrict__ Wq,
                     const float* __restrict__ Wk,
                     const float* __restrict__ Wv,
                     const float* __restrict__ Wg)
{
    GEMM_SMEM; GEMM_IDS;
    const int z = blockIdx.z;
    const float* __restrict__ Bw = (z == 0) ? Wq : (z == 1) ? Wk :
                                   (z == 2) ? Wv : Wg;
    float* __restrict__ Cc       = (z == 0) ? g_q : (z == 1) ? g_k :
                                   (z == 2) ? g_v : g_g1;

    GEMM_ACC_INIT;

    gemm_copy_tile(As[0], Bs[0], tid,
                   &X[(size_t)row0 * DIM], DIM, &Bw[col0], DIM);
    int buf = 0;
    for (int k0 = 32; k0 < DIM; k0 += 32) {
        CP_WAIT0(); __syncthreads();
        gemm_copy_tile(As[buf ^ 1], Bs[buf ^ 1], tid,
                       &X[(size_t)row0 * DIM + k0], DIM,
                       &Bw[(size_t)k0 * DIM + col0], DIM);
        gemm_compute(As[buf], Bs[buf], warp_m, warp_n, g, tg, acc);
        buf ^= 1;
    }
    CP_WAIT0(); __syncthreads();
    gemm_compute(As[buf], Bs[buf], warp_m, warp_n, g, tg, acc);

#pragma unroll
    for (int mt = 0; mt < 4; mt++) {
        int r0 = row0 + warp_m + mt * 16 + g;
#pragma unroll
        for (int nt = 0; nt < 4; nt++) {
            int c = col0 + warp_n + nt * 8 + tg * 2;
            float v0 = acc[mt][nt][0], v1 = acc[mt][nt][1];
            float v2 = acc[mt][nt][2], v3 = acc[mt][nt][3];
            if (z <= 1) { v0 = fmap(v0); v1 = fmap(v1); v2 = fmap(v2); v3 = fmap(v3); }
            *(float2*)&Cc[(size_t)r0      * DIM + c] = make_float2(v0, v1);
            *(float2*)&Cc[(size_t)(r0 + 8) * DIM + c] = make_float2(v2, v3);
        }
    }
}

// ---------------- O GEMM ----------------------------------------------------
__global__ __launch_bounds__(128)
void o_gemm_kernel(const float* __restrict__ Wo, const float* __restrict__ bias)
{
    GEMM_SMEM; GEMM_IDS;
    GEMM_ACC_INIT;

    gemm_copy_tile(As[0], Bs[0], tid,
                   &g_att[(size_t)row0 * DIM], DIM, &Wo[col0], DIM);
    int buf = 0;
    for (int k0 = 32; k0 < DIM; k0 += 32) {
        CP_WAIT0(); __syncthreads();
        gemm_copy_tile(As[buf ^ 1], Bs[buf ^ 1], tid,
                       &g_att[(size_t)row0 * DIM + k0], DIM,
                       &Wo[(size_t)k0 * DIM + col0], DIM);
        gemm_compute(As[buf], Bs[buf], warp_m, warp_n, g, tg, acc);
        buf ^= 1;
    }
    CP_WAIT0(); __syncthreads();
    gemm_compute(As[buf], Bs[buf], warp_m, warp_n, g, tg, acc);

#pragma unroll
    for (int mt = 0; mt < 4; mt++) {
        int r0 = row0 + warp_m + mt * 16 + g;
#pragma unroll
        for (int nt = 0; nt < 4; nt++) {
            int c = col0 + warp_n + nt * 8 + tg * 2;
            float b0 = bias[c], b1 = bias[c + 1];
            *(float2*)&g_o2[(size_t)r0      * DIM + c] =
                make_float2(acc[mt][nt][0] + b0, acc[mt][nt][1] + b1);
            *(float2*)&g_o2[(size_t)(r0 + 8) * DIM + c] =
                make_float2(acc[mt][nt][2] + b0, acc[mt][nt][3] + b1);
        }
    }
}

// ---------------- gate GEMM: K=512 (o2 @ Wg2), g1 precomputed ---------------
__global__ __launch_bounds__(128)
void gate_kernel(const float* __restrict__ X,
                 const float* __restrict__ Wg, const float* __restrict__ bg,
                 float* __restrict__ Out)
{
    GEMM_SMEM; GEMM_IDS;
    GEMM_ACC_INIT;
    const float* __restrict__ Wg2 = Wg + (size_t)DIM * DIM;

    gemm_copy_tile(As[0], Bs[0], tid,
                   &g_o2[(size_t)row0 * DIM], DIM, &Wg2[col0], DIM);
    int buf = 0;
    for (int k0 = 32; k0 < DIM; k0 += 32) {
        CP_WAIT0(); __syncthreads();
        gemm_copy_tile(As[buf ^ 1], Bs[buf ^ 1], tid,
                       &g_o2[(size_t)row0 * DIM + k0], DIM,
                       &Wg2[(size_t)k0 * DIM + col0], DIM);
        gemm_compute(As[buf], Bs[buf], warp_m, warp_n, g, tg, acc);
        buf ^= 1;
    }
    CP_WAIT0(); __syncthreads();
    gemm_compute(As[buf], Bs[buf], warp_m, warp_n, g, tg, acc);

#pragma unroll
    for (int mt = 0; mt < 4; mt++) {
        int r0 = row0 + warp_m + mt * 16 + g;
#pragma unroll
        for (int nt = 0; nt < 4; nt++) {
            int c = col0 + warp_n + nt * 8 + tg * 2;
            float b0 = bg[c], b1 = bg[c + 1];
#pragma unroll
            for (int half = 0; half < 2; half++) {
                int r = r0 + half * 8;
                float2 g1 = *(const float2*)&g_g1[(size_t)r * DIM + c];
                float z0 = acc[mt][nt][half * 2]     + g1.x + b0;
                float z1 = acc[mt][nt][half * 2 + 1] + g1.y + b1;
                float g0 = 1.f / (1.f + expf(-z0));
                float g1s = 1.f / (1.f + expf(-z1));
                float2 xv = *(const float2*)&X   [(size_t)r * DIM + c];
                float2 ov = *(const float2*)&g_o2[(size_t)r * DIM + c];
                *(float2*)&Out[(size_t)r * DIM + c] =
                    make_float2(xv.x + g0  * (ov.x - xv.x),
                                xv.y + g1s * (ov.y - xv.y));
            }
        }
    }
}

// ---------------- phase A: per-chunk kv sums (2d x 8e register tiles) -------
__global__ __launch_bounds__(256)
void chunk_sums_kernel()
{
    const int bid = blockIdx.x;
    const int c   = bid % NCHK;
    const int bh  = bid / NCHK;
    const int h   = bh % NH;
    const int b   = bh / NH;
    const int row0 = b * SEQ + c * CHK;
    const int col  = h * HD;

    __shared__ float ks[CHK][HD + 4];
    __shared__ float vs[CHK][HD + 4];
    for (int i = threadIdx.x; i < CHK * (HD / 4); i += 256) {
        int t = i / (HD / 4), d4 = (i % (HD / 4)) * 4;
        *(float4*)&ks[t][d4] =
            *(const float4*)&g_k[(size_t)(row0 + t) * DIM + col + d4];
        *(float4*)&vs[t][d4] =
            *(const float4*)&g_v[(size_t)(row0 + t) * DIM + col + d4];
    }
    __syncthreads();

    const int d0 = (threadIdx.x >> 3) * 2;      // 0,2,..,62
    const int e0 = (threadIdx.x & 7) * 8;       // 0,8,..,56
    float acc[2][8];
#pragma unroll
    for (int i = 0; i < 2; i++)
#pragma unroll
        for (int j = 0; j < 8; j++) acc[i][j] = 0.f;

#pragma unroll
    for (int t = 0; t < CHK; t++) {
        float k0 = ks[t][d0], k1 = ks[t][d0 + 1];
        float4 vA = *(const float4*)&vs[t][e0];
        float4 vB = *(const float4*)&vs[t][e0 + 4];
        acc[0][0] += k0 * vA.x; acc[0][1] += k0 * vA.y;
        acc[0][2] += k0 * vA.z; acc[0][3] += k0 * vA.w;
        acc[0][4] += k0 * vB.x; acc[0][5] += k0 * vB.y;
        acc[0][6] += k0 * vB.z; acc[0][7] += k0 * vB.w;
        acc[1][0] += k1 * vA.x; acc[1][1] += k1 * vA.y;
        acc[1][2] += k1 * vA.z; acc[1][3] += k1 * vA.w;
        acc[1][4] += k1 * vB.x; acc[1][5] += k1 * vB.y;
        acc[1][6] += k1 * vB.z; acc[1][7] += k1 * vB.w;
    }
    const int base = bid * HD * HD;
#pragma unroll
    for (int i = 0; i < 2; i++) {
        *(float4*)&g_kv[base + (d0 + i) * HD + e0] =
            make_float4(acc[i][0], acc[i][1], acc[i][2], acc[i][3]);
        *(float4*)&g_kv[base + (d0 + i) * HD + e0 + 4] =
            make_float4(acc[i][4], acc[i][5], acc[i][6], acc[i][7]);
    }

    if (threadIdx.x < HD) {
        float a = 0.f;
#pragma unroll
        for (int t = 0; t < CHK; t++) a += ks[t][threadIdx.x];
        g_ks[bid * HD + threadIdx.x] = a;
    }
}

// ---------------- phase B: exclusive prefix, one element per thread ---------
__global__ __launch_bounds__(256)
void prefix_kernel()
{
    const int bh    = blockIdx.x >> 4;          // 0..15
    const int slice = blockIdx.x & 15;          // 0..15
    const int i     = slice * 256 + threadIdx.x;  // 0..4095
    float run = 0.f;
    for (int c = 0; c < NCHK; c++) {
        int idx = (bh * NCHK + c) * HD * HD + i;
        float t = g_kv[idx];
        g_kv[idx] = run;
        run += t;
    }
    if (slice == 0 && threadIdx.x < HD) {
        float r = 0.f;
        for (int c = 0; c < NCHK; c++) {
            int idx = (bh * NCHK + c) * HD + threadIdx.x;
            float t = g_ks[idx];
            g_ks[idx] = r;
            r += t;
        }
    }
}

// ---------------- phase C: intra-chunk attention (Sc aliases kst) -----------
__global__ __launch_bounds__(128)
void chunk_out_kernel()
{
    const int bid = blockIdx.x;
    const int c   = bid % NCHK;
    const int bh  = bid / NCHK;
    const int h   = bh % NH;
    const int b   = bh / NH;
    const int row0 = b * SEQ + c * CHK;
    const int col  = h * HD;

    __shared__ float qs [CHK][HD + 4];
    __shared__ float kst_sc[HD * (CHK + 4)];   // kst[64][36]; Sc reuses [32][36]
    __shared__ float vs [CHK][HD + 4];
    __shared__ float kvp[HD][HD + 4];
    __shared__ float kp [HD];
    __shared__ float den[CHK];

    float (*kst)[CHK + 4] = (float(*)[CHK + 4])kst_sc;
    float (*Sc) [CHK + 4] = (float(*)[CHK + 4])kst_sc;

    const int tid = threadIdx.x;
    for (int i = tid; i < CHK * (HD / 4); i += 128) {
        int t = i / (HD / 4), d4 = (i % (HD / 4)) * 4;
        *(float4*)&qs[t][d4] =
            *(const float4*)&g_q[(size_t)(row0 + t) * DIM + col + d4];
        float4 kv4 = *(const float4*)&g_k[(size_t)(row0 + t) * DIM + col + d4];
        kst[d4+0][t] = kv4.x; kst[d4+1][t] = kv4.y;
        kst[d4+2][t] = kv4.z; kst[d4+3][t] = kv4.w;
        *(float4*)&vs[t][d4] =
            *(const float4*)&g_v[(size_t)(row0 + t) * DIM + col + d4];
    }
    const int base = bid * HD * HD;
    for (int i = tid; i < HD * (HD / 4); i += 128) {
        int d = i / (HD / 4), e4 = (i % (HD / 4)) * 4;
        *(float4*)&kvp[d][e4] = *(const float4*)&g_kv[base + d * HD + e4];
    }
    if (tid < HD) kp[tid] = g_ks[bid * HD + tid];
    __syncthreads();

    const int sg = tid >> 3;          // 0..15
    const int s0 = sg * 2;            // 0,2,..,30
    const int t0 = (tid & 7) * 4;

    // scores: 2s x 4t per thread, into registers first (kst still live)
    float a0[4] = {0.f, 0.f, 0.f, 0.f};
    float a1[4] = {0.f, 0.f, 0.f, 0.f};
#pragma unroll
    for (int d0 = 0; d0 < HD; d0 += 4) {
        float4 qA = *(const float4*)&qs[s0][d0];
        float4 qB = *(const float4*)&qs[s0 + 1][d0];
        float4 kA = *(const float4*)&kst[d0+0][t0];
        float4 kB = *(const float4*)&kst[d0+1][t0];
        float4 kC = *(const float4*)&kst[d0+2][t0];
        float4 kD = *(const float4*)&kst[d0+3][t0];
        a0[0] += qA.x*kA.x + qA.y*kB.x + qA.z*kC.x + qA.w*kD.x;
        a0[1] += qA.x*kA.y + qA.y*kB.y + qA.z*kC.y + qA.w*kD.y;
        a0[2] += qA.x*kA.z + qA.y*kB.z + qA.z*kC.z + qA.w*kD.z;
        a0[3] += qA.x*kA.w + qA.y*kB.w + qA.z*kC.w + qA.w*kD.w;
        a1[0] += qB.x*kA.x + qB.y*kB.x + qB.z*kC.x + qB.w*kD.x;
        a1[1] += qB.x*kA.y + qB.y*kB.y + qB.z*kC.y + qB.w*kD.y;
        a1[2] += qB.x*kA.z + qB.y*kB.z + qB.z*kC.z + qB.w*kD.z;
        a1[3] += qB.x*kA.w + qB.y*kB.w + qB.z*kC.w + qB.w*kD.w;
    }
    __syncthreads();   // all kst reads done; safe to overwrite with Sc
#pragma unroll
    for (int j = 0; j < 4; j++) {
        Sc[s0    ][t0 + j] = (t0 + j <= s0    ) ? a0[j] : 0.f;
        Sc[s0 + 1][t0 + j] = (t0 + j <= s0 + 1) ? a1[j] : 0.f;
    }
    __syncthreads();

    if (tid < CHK) {
        const int s = tid;
        float a = 0.f;
#pragma unroll
        for (int d0 = 0; d0 < HD; d0 += 4) {
            float4 q4 = *(const float4*)&qs[s][d0];
            float4 k4 = *(const float4*)&kp[d0];
            a += q4.x*k4.x + q4.y*k4.y + q4.z*k4.z + q4.w*k4.w;
        }
#pragma unroll
        for (int tt = 0; tt < CHK; tt += 4) {
            float4 s4 = *(const float4*)&Sc[s][tt];
            a += s4.x + s4.y + s4.z + s4.w;
        }
        den[s] = a + 1e-6f;
    }
    __syncthreads();

    // output: 2s x 8e per thread
    {
        const int e0 = (tid & 7) * 8;
        float b0[8], b1[8];
#pragma unroll
        for (int j = 0; j < 8; j++) { b0[j] = 0.f; b1[j] = 0.f; }

#pragma unroll
        for (int d0 = 0; d0 < HD; d0 += 4) {
            float4 qA = *(const float4*)&qs[s0][d0];
            float4 qB = *(const float4*)&qs[s0 + 1][d0];
            float qa[4] = {qA.x, qA.y, qA.z, qA.w};
            float qb[4] = {qB.x, qB.y, qB.z, qB.w};
#pragma unroll
            for (int dd = 0; dd < 4; dd++) {
                float4 vA = *(const float4*)&kvp[d0 + dd][e0];
                float4 vB = *(const float4*)&kvp[d0 + dd][e0 + 4];
                b0[0] += qa[dd] * vA.x; b0[1] += qa[dd] * vA.y;
                b0[2] += qa[dd] * vA.z; b0[3] += qa[dd] * vA.w;
                b0[4] += qa[dd] * vB.x; b0[5] += qa[dd] * vB.y;
                b0[6] += qa[dd] * vB.z; b0[7] += qa[dd] * vB.w;
                b1[0] += qb[dd] * vA.x; b1[1] += qb[dd] * vA.y;
                b1[2] += qb[dd] * vA.z; b1[3] += qb[dd] * vA.w;
                b1[4] += qb[dd] * vB.x; b1[5] += qb[dd] * vB.y;
                b1[6] += qb[dd] * vB.z; b1[7] += qb[dd] * vB.w;
            }
        }
#pragma unroll
        for (int tt0 = 0; tt0 < CHK; tt0 += 4) {
            float4 sA = *(const float4*)&Sc[s0][tt0];
            float4 sB = *(const float4*)&Sc[s0 + 1][tt0];
            float sa[4] = {sA.x, sA.y, sA.z, sA.w};
            float sb[4] = {sB.x, sB.y, sB.z, sB.w};
#pragma unroll
            for (int tt = 0; tt < 4; tt++) {
                float4 vA = *(const float4*)&vs[tt0 + tt][e0];
                float4 vB = *(const float4*)&vs[tt0 + tt][e0 + 4];
                b0[0] += sa[tt] * vA.x; b0[1] += sa[tt] * vA.y;
                b0[2] += sa[tt] * vA.z; b0[3] += sa[tt] * vA.w;
                b0[4] += sa[tt] * vB.x; b0[5] += sa[tt] * vB.y;
                b0[6] += sa[tt] * vB.z; b0[7] += sa[tt] * vB.w;
                b1[0] += sb[tt] * vA.x; b1[1] += sb[tt] * vA.y;
                b1[2] += sb[tt] * vA.z; b1[3] += sb[tt] * vA.w;
                b1[4] += sb[tt] * vB.x; b1[5] += sb[tt] * vB.y;
                b1[6] += sb[tt] * vB.z; b1[7] += sb[tt] * vB.w;
            }
        }
        const float inv0 = 1.f / den[s0];
        const float inv1 = 1.f / den[s0 + 1];
        float* d0p = &g_att[(size_t)(row0 + s0)     * DIM + col + e0];
        float* d1p = &g_att[(size_t)(row0 + s0 + 1) * DIM + col + e0];
        *(float4*)&d0p[0] = make_float4(b0[0]*inv0, b0[1]*inv0, b0[2]*inv0, b0[3]*inv0);
        *(float4*)&d0p[4] = make_float4(b0[4]*inv0, b0[5]*inv0, b0[6]*inv0, b0[7]*inv0);
        *(float4*)&d1p[0] = make_float4(b1[0]*inv1, b1[1]*inv1, b1[2]*inv1, b1[3]*inv1);
        *(float4*)&d1p[4] = make_float4(b1[4]*inv1, b1[5]*inv1, b1[6]*inv1, b1[7]*inv1);
    }
}

// ---------------- launcher --------------------------------------------------
extern "C" void kernel_launch(void* const* d_in, const int* in_sizes, int n_in,
                              void* d_out, int out_size)
{
    const float* x  = (const float*)d_in[0];
    const float* Wq = (const float*)d_in[1];
    const float* Wk = (const float*)d_in[2];
    const float* Wv = (const float*)d_in[3];
    const float* Wo = (const float*)d_in[4];
    const float* bo = (const float*)d_in[5];
    const float* Wg = (const float*)d_in[6];
    const float* bg = (const float*)d_in[7];
    float* out = (float*)d_out;

    cudaFuncSetAttribute(qkv_gemm_kernel,
        cudaFuncAttributeMaxDynamicSharedMemorySize, GEMM_SMEM_BYTES);
    cudaFuncSetAttribute(o_gemm_kernel,
        cudaFuncAttributeMaxDynamicSharedMemorySize, GEMM_SMEM_BYTES);
    cudaFuncSetAttribute(gate_kernel,
        cudaFuncAttributeMaxDynamicSharedMemorySize, GEMM_SMEM_BYTES);

    dim3 grid (DIM / 64, MROWS / 128, 1);   // (8, 16)
    dim3 grid4(DIM / 64, MROWS / 128, 4);   // fused QKV + G1

    qkv_gemm_kernel<<<grid4, 128, GEMM_SMEM_BYTES>>>(x, Wq, Wk, Wv, Wg);
    chunk_sums_kernel<<<NBLK, 256>>>();
    prefix_kernel<<<NBH * 16, 256>>>();
    chunk_out_kernel<<<NBLK, 128>>>();
    o_gemm_kernel<<<grid, 128, GEMM_SMEM_BYTES>>>(Wo, bo);
    gate_kernel<<<grid, 128, GEMM_SMEM_BYTES>>>(x, Wg, bg, out);
}

// round 10
// speedup vs baseline: 2.9464x; 1.0427x over previous
#include <cuda_runtime.h>
#include <math.h>
#include <stdint.h>

#define BATCH 2
#define SEQ   1024
#define DIM   512
#define NH    8
#define HD    64
#define MROWS (BATCH*SEQ)      // 2048
#define CHK   32
#define NCHK  (SEQ/CHK)        // 32
#define NBH   (BATCH*NH)       // 16
#define NBLK  (NBH*NCHK)       // 512

// ---------------- scratch ---------------------------------------------------
__device__ float g_q  [MROWS*DIM];
__device__ float g_k  [MROWS*DIM];
__device__ float g_v  [MROWS*DIM];
__device__ float g_att[MROWS*DIM];
__device__ float g_o2 [MROWS*DIM];
__device__ float g_g1 [MROWS*DIM];   // x @ Wg[:512]  (precomputed with QKV)
__device__ float g_kv [NBLK*HD*HD];
__device__ float g_ks [NBLK*HD];

__device__ __forceinline__ float fmap(float t) {
    return t > 0.f ? t + 1.f : expf(t);
}

__device__ __forceinline__ void mma_tf32(float c[4],
    uint32_t a0, uint32_t a1, uint32_t a2, uint32_t a3,
    uint32_t b0, uint32_t b1)
{
    asm volatile(
        "mma.sync.aligned.m16n8k8.row.col.f32.tf32.tf32.f32 "
        "{%0,%1,%2,%3},{%4,%5,%6,%7},{%8,%9},{%0,%1,%2,%3};"
        : "+f"(c[0]), "+f"(c[1]), "+f"(c[2]), "+f"(c[3])
        : "r"(a0), "r"(a1), "r"(a2), "r"(a3), "r"(b0), "r"(b1));
}

__device__ __forceinline__ void cp16(void* smem_dst, const void* gsrc) {
    uint32_t d = (uint32_t)__cvta_generic_to_shared(smem_dst);
    asm volatile("cp.async.cg.shared.global [%0], [%1], 16;" :: "r"(d), "l"(gsrc));
}
#define CP_COMMIT() asm volatile("cp.async.commit_group;")
#define CP_WAIT0()  asm volatile("cp.async.wait_group 0;")

// ======================= tf32 GEMM framework ================================
// BM=128, BN=64, BK=32, 128 threads, 4 warps as 2(M)x2(N), warp tile 64x32.
#define AS_STRIDE 36
#define BS_STRIDE 72
#define AS_WORDS  (128 * AS_STRIDE)
#define BS_WORDS  (32 * BS_STRIDE)
#define GEMM_SMEM_BYTES ((2 * AS_WORDS + 2 * BS_WORDS) * 4)   // 55296

typedef uint32_t AsBuf[128][AS_STRIDE];
typedef uint32_t BsBuf[32][BS_STRIDE];

#define GEMM_SMEM \
    extern __shared__ uint32_t dynsmem[]; \
    AsBuf* As = (AsBuf*)dynsmem; \
    BsBuf* Bs = (BsBuf*)(dynsmem + 2 * AS_WORDS);

#define GEMM_IDS \
    const int tid  = threadIdx.x; \
    const int lane = tid & 31, wid = tid >> 5; \
    const int g    = lane >> 2, tg = lane & 3; \
    const int warp_m = (wid >> 1) * 64, warp_n = (wid & 1) * 32; \
    const int row0 = blockIdx.y * 128, col0 = blockIdx.x * 64;

__device__ __forceinline__ void gemm_copy_tile(
    uint32_t (*Asb)[AS_STRIDE], uint32_t (*Bsb)[BS_STRIDE], int tid,
    const float* Ag, size_t lda, const float* Bg, size_t ldb)
{
    const int ar = tid >> 3;            // 0..15
    const int ac = (tid & 7) * 4;       // 0,4,..,28
#pragma unroll
    for (int p = 0; p < 8; p++)
        cp16(&Asb[ar + p * 16][ac], Ag + (size_t)(ar + p * 16) * lda + ac);
#pragma unroll
    for (int p = 0; p < 4; p++) {
        int idx = tid + p * 128;
        int br  = idx >> 4;             // 0..31
        int bc  = (idx & 15) * 4;       // 0,4,..,60
        cp16(&Bsb[br][bc], Bg + (size_t)br * ldb + bc);
    }
    CP_COMMIT();
}

__device__ __forceinline__ void gemm_compute(
    uint32_t (*Asb)[AS_STRIDE], uint32_t (*Bsb)[BS_STRIDE],
    int warp_m, int warp_n, int g, int tg, float acc[4][4][4])
{
#pragma unroll
    for (int ks = 0; ks < 4; ks++) {
        uint32_t af[4][4];
#pragma unroll
        for (int mt = 0; mt < 4; mt++) {
            int base = warp_m + mt * 16;
            af[mt][0] = Asb[base + g    ][ks * 8 + tg];
            af[mt][1] = Asb[base + g + 8][ks * 8 + tg];
            af[mt][2] = Asb[base + g    ][ks * 8 + tg + 4];
            af[mt][3] = Asb[base + g + 8][ks * 8 + tg + 4];
        }
        uint32_t bf[4][2];
#pragma unroll
        for (int nt = 0; nt < 4; nt++) {
            int col = warp_n + nt * 8 + g;
            bf[nt][0] = Bsb[ks * 8 + tg    ][col];
            bf[nt][1] = Bsb[ks * 8 + tg + 4][col];
        }
#pragma unroll
        for (int mt = 0; mt < 4; mt++)
#pragma unroll
            for (int nt = 0; nt < 4; nt++)
                mma_tf32(acc[mt][nt], af[mt][0], af[mt][1], af[mt][2], af[mt][3],
                         bf[nt][0], bf[nt][1]);
    }
}

#define GEMM_ACC_INIT \
    float acc[4][4][4]; \
    _Pragma("unroll") \
    for (int mt = 0; mt < 4; mt++) \
        _Pragma("unroll") \
        for (int nt = 0; nt < 4; nt++) \
            _Pragma("unroll") \
            for (int i = 0; i < 4; i++) acc[mt][nt][i] = 0.f;

// ---------------- fused QKV+G1 GEMM (z: 0=q,1=k,2=v,3=g1) -------------------
__global__ __launch_bounds__(128)
void qkv_gemm_kernel(const float* __restrict__ X,
                     const float* __restrict__ Wq,
                     const float* __restrict__ Wk,
                     const float* __restrict__ Wv,
                     const float* __restrict__ Wg)
{
    GEMM_SMEM; GEMM_IDS;
    const int z = blockIdx.z;
    const float* __restrict__ Bw = (z == 0) ? Wq : (z == 1) ? Wk :
                                   (z == 2) ? Wv : Wg;
    float* __restrict__ Cc       = (z == 0) ? g_q : (z == 1) ? g_k :
                                   (z == 2) ? g_v : g_g1;

    GEMM_ACC_INIT;

    gemm_copy_tile(As[0], Bs[0], tid,
                   &X[(size_t)row0 * DIM], DIM, &Bw[col0], DIM);
    int buf = 0;
    for (int k0 = 32; k0 < DIM; k0 += 32) {
        CP_WAIT0(); __syncthreads();
        gemm_copy_tile(As[buf ^ 1], Bs[buf ^ 1], tid,
                       &X[(size_t)row0 * DIM + k0], DIM,
                       &Bw[(size_t)k0 * DIM + col0], DIM);
        gemm_compute(As[buf], Bs[buf], warp_m, warp_n, g, tg, acc);
        buf ^= 1;
    }
    CP_WAIT0(); __syncthreads();
    gemm_compute(As[buf], Bs[buf], warp_m, warp_n, g, tg, acc);

#pragma unroll
    for (int mt = 0; mt < 4; mt++) {
        int r0 = row0 + warp_m + mt * 16 + g;
#pragma unroll
        for (int nt = 0; nt < 4; nt++) {
            int c = col0 + warp_n + nt * 8 + tg * 2;
            float v0 = acc[mt][nt][0], v1 = acc[mt][nt][1];
            float v2 = acc[mt][nt][2], v3 = acc[mt][nt][3];
            if (z <= 1) { v0 = fmap(v0); v1 = fmap(v1); v2 = fmap(v2); v3 = fmap(v3); }
            *(float2*)&Cc[(size_t)r0      * DIM + c] = make_float2(v0, v1);
            *(float2*)&Cc[(size_t)(r0 + 8) * DIM + c] = make_float2(v2, v3);
        }
    }
}

// ---------------- O GEMM ----------------------------------------------------
__global__ __launch_bounds__(128)
void o_gemm_kernel(const float* __restrict__ Wo, const float* __restrict__ bias)
{
    GEMM_SMEM; GEMM_IDS;
    GEMM_ACC_INIT;

    gemm_copy_tile(As[0], Bs[0], tid,
                   &g_att[(size_t)row0 * DIM], DIM, &Wo[col0], DIM);
    int buf = 0;
    for (int k0 = 32; k0 < DIM; k0 += 32) {
        CP_WAIT0(); __syncthreads();
        gemm_copy_tile(As[buf ^ 1], Bs[buf ^ 1], tid,
                       &g_att[(size_t)row0 * DIM + k0], DIM,
                       &Wo[(size_t)k0 * DIM + col0], DIM);
        gemm_compute(As[buf], Bs[buf], warp_m, warp_n, g, tg, acc);
        buf ^= 1;
    }
    CP_WAIT0(); __syncthreads();
    gemm_compute(As[buf], Bs[buf], warp_m, warp_n, g, tg, acc);

#pragma unroll
    for (int mt = 0; mt < 4; mt++) {
        int r0 = row0 + warp_m + mt * 16 + g;
#pragma unroll
        for (int nt = 0; nt < 4; nt++) {
            int c = col0 + warp_n + nt * 8 + tg * 2;
            float b0 = bias[c], b1 = bias[c + 1];
            *(float2*)&g_o2[(size_t)r0      * DIM + c] =
                make_float2(acc[mt][nt][0] + b0, acc[mt][nt][1] + b1);
            *(float2*)&g_o2[(size_t)(r0 + 8) * DIM + c] =
                make_float2(acc[mt][nt][2] + b0, acc[mt][nt][3] + b1);
        }
    }
}

// ---------------- gate GEMM: K=512 (o2 @ Wg2), g1 precomputed ---------------
__global__ __launch_bounds__(128)
void gate_kernel(const float* __restrict__ X,
                 const float* __restrict__ Wg, const float* __restrict__ bg,
                 float* __restrict__ Out)
{
    GEMM_SMEM; GEMM_IDS;
    GEMM_ACC_INIT;
    const float* __restrict__ Wg2 = Wg + (size_t)DIM * DIM;

    gemm_copy_tile(As[0], Bs[0], tid,
                   &g_o2[(size_t)row0 * DIM], DIM, &Wg2[col0], DIM);
    int buf = 0;
    for (int k0 = 32; k0 < DIM; k0 += 32) {
        CP_WAIT0(); __syncthreads();
        gemm_copy_tile(As[buf ^ 1], Bs[buf ^ 1], tid,
                       &g_o2[(size_t)row0 * DIM + k0], DIM,
                       &Wg2[(size_t)k0 * DIM + col0], DIM);
        gemm_compute(As[buf], Bs[buf], warp_m, warp_n, g, tg, acc);
        buf ^= 1;
    }
    CP_WAIT0(); __syncthreads();
    gemm_compute(As[buf], Bs[buf], warp_m, warp_n, g, tg, acc);

#pragma unroll
    for (int mt = 0; mt < 4; mt++) {
        int r0 = row0 + warp_m + mt * 16 + g;
#pragma unroll
        for (int nt = 0; nt < 4; nt++) {
            int c = col0 + warp_n + nt * 8 + tg * 2;
            float b0 = bg[c], b1 = bg[c + 1];
#pragma unroll
            for (int half = 0; half < 2; half++) {
                int r = r0 + half * 8;
                float2 g1 = *(const float2*)&g_g1[(size_t)r * DIM + c];
                float z0 = acc[mt][nt][half * 2]     + g1.x + b0;
                float z1 = acc[mt][nt][half * 2 + 1] + g1.y + b1;
                float g0 = 1.f / (1.f + expf(-z0));
                float g1s = 1.f / (1.f + expf(-z1));
                float2 xv = *(const float2*)&X   [(size_t)r * DIM + c];
                float2 ov = *(const float2*)&g_o2[(size_t)r * DIM + c];
                *(float2*)&Out[(size_t)r * DIM + c] =
                    make_float2(xv.x + g0  * (ov.x - xv.x),
                                xv.y + g1s * (ov.y - xv.y));
            }
        }
    }
}

// ---------------- phase A: per-chunk kv sums (2d x 8e register tiles) -------
__global__ __launch_bounds__(256)
void chunk_sums_kernel()
{
    const int bid = blockIdx.x;
    const int c   = bid % NCHK;
    const int bh  = bid / NCHK;
    const int h   = bh % NH;
    const int b   = bh / NH;
    const int row0 = b * SEQ + c * CHK;
    const int col  = h * HD;

    __shared__ float ks[CHK][HD + 4];
    __shared__ float vs[CHK][HD + 4];
    for (int i = threadIdx.x; i < CHK * (HD / 4); i += 256) {
        int t = i / (HD / 4), d4 = (i % (HD / 4)) * 4;
        *(float4*)&ks[t][d4] =
            *(const float4*)&g_k[(size_t)(row0 + t) * DIM + col + d4];
        *(float4*)&vs[t][d4] =
            *(const float4*)&g_v[(size_t)(row0 + t) * DIM + col + d4];
    }
    __syncthreads();

    const int d0 = (threadIdx.x >> 3) * 2;      // 0,2,..,62
    const int e0 = (threadIdx.x & 7) * 8;       // 0,8,..,56
    float acc[2][8];
#pragma unroll
    for (int i = 0; i < 2; i++)
#pragma unroll
        for (int j = 0; j < 8; j++) acc[i][j] = 0.f;

#pragma unroll
    for (int t = 0; t < CHK; t++) {
        float k0 = ks[t][d0], k1 = ks[t][d0 + 1];
        float4 vA = *(const float4*)&vs[t][e0];
        float4 vB = *(const float4*)&vs[t][e0 + 4];
        acc[0][0] += k0 * vA.x; acc[0][1] += k0 * vA.y;
        acc[0][2] += k0 * vA.z; acc[0][3] += k0 * vA.w;
        acc[0][4] += k0 * vB.x; acc[0][5] += k0 * vB.y;
        acc[0][6] += k0 * vB.z; acc[0][7] += k0 * vB.w;
        acc[1][0] += k1 * vA.x; acc[1][1] += k1 * vA.y;
        acc[1][2] += k1 * vA.z; acc[1][3] += k1 * vA.w;
        acc[1][4] += k1 * vB.x; acc[1][5] += k1 * vB.y;
        acc[1][6] += k1 * vB.z; acc[1][7] += k1 * vB.w;
    }
    const int base = bid * HD * HD;
#pragma unroll
    for (int i = 0; i < 2; i++) {
        *(float4*)&g_kv[base + (d0 + i) * HD + e0] =
            make_float4(acc[i][0], acc[i][1], acc[i][2], acc[i][3]);
        *(float4*)&g_kv[base + (d0 + i) * HD + e0 + 4] =
            make_float4(acc[i][4], acc[i][5], acc[i][6], acc[i][7]);
    }

    if (threadIdx.x < HD) {
        float a = 0.f;
#pragma unroll
        for (int t = 0; t < CHK; t++) a += ks[t][threadIdx.x];
        g_ks[bid * HD + threadIdx.x] = a;
    }
}

// ---------------- phase B: exclusive prefix, one element per thread ---------
__global__ __launch_bounds__(256)
void prefix_kernel()
{
    const int bh    = blockIdx.x >> 4;          // 0..15
    const int slice = blockIdx.x & 15;          // 0..15
    const int i     = slice * 256 + threadIdx.x;  // 0..4095
    float run = 0.f;
    for (int c = 0; c < NCHK; c++) {
        int idx = (bh * NCHK + c) * HD * HD + i;
        float t = g_kv[idx];
        g_kv[idx] = run;
        run += t;
    }
    if (slice == 0 && threadIdx.x < HD) {
        float r = 0.f;
        for (int c = 0; c < NCHK; c++) {
            int idx = (bh * NCHK + c) * HD + threadIdx.x;
            float t = g_ks[idx];
            g_ks[idx] = r;
            r += t;
        }
    }
}

// ---------------- phase C: intra-chunk attention (256 thr, 2s x 4e) ---------
__global__ __launch_bounds__(256)
void chunk_out_kernel()
{
    const int bid = blockIdx.x;
    const int c   = bid % NCHK;
    const int bh  = bid / NCHK;
    const int h   = bh % NH;
    const int b   = bh / NH;
    const int row0 = b * SEQ + c * CHK;
    const int col  = h * HD;

    __shared__ float qs [CHK][HD + 4];
    __shared__ float kst_sc[HD * (CHK + 4)];   // kst[64][36]; Sc reuses [32][36]
    __shared__ float vs [CHK][HD + 4];
    __shared__ float kvp[HD][HD + 4];
    __shared__ float kp [HD];
    __shared__ float den[CHK];

    float (*kst)[CHK + 4] = (float(*)[CHK + 4])kst_sc;
    float (*Sc) [CHK + 4] = (float(*)[CHK + 4])kst_sc;

    const int tid = threadIdx.x;
    for (int i = tid; i < CHK * (HD / 4); i += 256) {
        int t = i / (HD / 4), d4 = (i % (HD / 4)) * 4;
        *(float4*)&qs[t][d4] =
            *(const float4*)&g_q[(size_t)(row0 + t) * DIM + col + d4];
        float4 kv4 = *(const float4*)&g_k[(size_t)(row0 + t) * DIM + col + d4];
        kst[d4+0][t] = kv4.x; kst[d4+1][t] = kv4.y;
        kst[d4+2][t] = kv4.z; kst[d4+3][t] = kv4.w;
        *(float4*)&vs[t][d4] =
            *(const float4*)&g_v[(size_t)(row0 + t) * DIM + col + d4];
    }
    const int base = bid * HD * HD;
    for (int i = tid; i < HD * (HD / 4); i += 256) {
        int d = i / (HD / 4), e4 = (i % (HD / 4)) * 4;
        *(float4*)&kvp[d][e4] = *(const float4*)&g_kv[base + d * HD + e4];
    }
    if (tid < HD) kp[tid] = g_ks[bid * HD + tid];
    __syncthreads();

    const int s0 = (tid >> 4) * 2;    // 0,2,..,30

    // scores: 2s x 2t per thread (256 threads cover 32x32)
    {
        const int t0 = (tid & 15) * 2;
        float a0[2] = {0.f, 0.f};
        float a1[2] = {0.f, 0.f};
#pragma unroll
        for (int d0 = 0; d0 < HD; d0 += 4) {
            float4 qA = *(const float4*)&qs[s0][d0];
            float4 qB = *(const float4*)&qs[s0 + 1][d0];
            float2 kA = *(const float2*)&kst[d0+0][t0];
            float2 kB = *(const float2*)&kst[d0+1][t0];
            float2 kC = *(const float2*)&kst[d0+2][t0];
            float2 kD = *(const float2*)&kst[d0+3][t0];
            a0[0] += qA.x*kA.x + qA.y*kB.x + qA.z*kC.x + qA.w*kD.x;
            a0[1] += qA.x*kA.y + qA.y*kB.y + qA.z*kC.y + qA.w*kD.y;
            a1[0] += qB.x*kA.x + qB.y*kB.x + qB.z*kC.x + qB.w*kD.x;
            a1[1] += qB.x*kA.y + qB.y*kB.y + qB.z*kC.y + qB.w*kD.y;
        }
        __syncthreads();   // all kst reads done; safe to overwrite with Sc
#pragma unroll
        for (int j = 0; j < 2; j++) {
            Sc[s0    ][t0 + j] = (t0 + j <= s0    ) ? a0[j] : 0.f;
            Sc[s0 + 1][t0 + j] = (t0 + j <= s0 + 1) ? a1[j] : 0.f;
        }
    }
    __syncthreads();

    if (tid < CHK) {
        const int s = tid;
        float a = 0.f;
#pragma unroll
        for (int d0 = 0; d0 < HD; d0 += 4) {
            float4 q4 = *(const float4*)&qs[s][d0];
            float4 k4 = *(const float4*)&kp[d0];
            a += q4.x*k4.x + q4.y*k4.y + q4.z*k4.z + q4.w*k4.w;
        }
#pragma unroll
        for (int tt = 0; tt < CHK; tt += 4) {
            float4 s4 = *(const float4*)&Sc[s][tt];
            a += s4.x + s4.y + s4.z + s4.w;
        }
        den[s] = a + 1e-6f;
    }
    __syncthreads();

    // output: 2s x 4e per thread (256 threads cover 32x64)
    {
        const int e0 = (tid & 15) * 4;
        float b0[4] = {0.f, 0.f, 0.f, 0.f};
        float b1[4] = {0.f, 0.f, 0.f, 0.f};

#pragma unroll
        for (int d0 = 0; d0 < HD; d0 += 4) {
            float4 qA = *(const float4*)&qs[s0][d0];
            float4 qB = *(const float4*)&qs[s0 + 1][d0];
            float qa[4] = {qA.x, qA.y, qA.z, qA.w};
            float qb[4] = {qB.x, qB.y, qB.z, qB.w};
#pragma unroll
            for (int dd = 0; dd < 4; dd++) {
                float4 vA = *(const float4*)&kvp[d0 + dd][e0];
                b0[0] += qa[dd] * vA.x; b0[1] += qa[dd] * vA.y;
                b0[2] += qa[dd] * vA.z; b0[3] += qa[dd] * vA.w;
                b1[0] += qb[dd] * vA.x; b1[1] += qb[dd] * vA.y;
                b1[2] += qb[dd] * vA.z; b1[3] += qb[dd] * vA.w;
            }
        }
#pragma unroll
        for (int tt0 = 0; tt0 < CHK; tt0 += 4) {
            float4 sA = *(const float4*)&Sc[s0][tt0];
            float4 sB = *(const float4*)&Sc[s0 + 1][tt0];
            float sa[4] = {sA.x, sA.y, sA.z, sA.w};
            float sb[4] = {sB.x, sB.y, sB.z, sB.w};
#pragma unroll
            for (int tt = 0; tt < 4; tt++) {
                float4 vA = *(const float4*)&vs[tt0 + tt][e0];
                b0[0] += sa[tt] * vA.x; b0[1] += sa[tt] * vA.y;
                b0[2] += sa[tt] * vA.z; b0[3] += sa[tt] * vA.w;
                b1[0] += sb[tt] * vA.x; b1[1] += sb[tt] * vA.y;
                b1[2] += sb[tt] * vA.z; b1[3] += sb[tt] * vA.w;
            }
        }
        const float inv0 = 1.f / den[s0];
        const float inv1 = 1.f / den[s0 + 1];
        float* d0p = &g_att[(size_t)(row0 + s0)     * DIM + col + e0];
        float* d1p = &g_att[(size_t)(row0 + s0 + 1) * DIM + col + e0];
        *(float4*)d0p = make_float4(b0[0]*inv0, b0[1]*inv0, b0[2]*inv0, b0[3]*inv0);
        *(float4*)d1p = make_float4(b1[0]*inv1, b1[1]*inv1, b1[2]*inv1, b1[3]*inv1);
    }
}

// ---------------- launcher --------------------------------------------------
extern "C" void kernel_launch(void* const* d_in, const int* in_sizes, int n_in,
                              void* d_out, int out_size)
{
    const float* x  = (const float*)d_in[0];
    const float* Wq = (const float*)d_in[1];
    const float* Wk = (const float*)d_in[2];
    const float* Wv = (const float*)d_in[3];
    const float* Wo = (const float*)d_in[4];
    const float* bo = (const float*)d_in[5];
    const float* Wg = (const float*)d_in[6];
    const float* bg = (const float*)d_in[7];
    float* out = (float*)d_out;

    cudaFuncSetAttribute(qkv_gemm_kernel,
        cudaFuncAttributeMaxDynamicSharedMemorySize, GEMM_SMEM_BYTES);
    cudaFuncSetAttribute(o_gemm_kernel,
        cudaFuncAttributeMaxDynamicSharedMemorySize, GEMM_SMEM_BYTES);
    cudaFuncSetAttribute(gate_kernel,
        cudaFuncAttributeMaxDynamicSharedMemorySize, GEMM_SMEM_BYTES);

    dim3 grid (DIM / 64, MROWS / 128, 1);   // (8, 16)
    dim3 grid4(DIM / 64, MROWS / 128, 4);   // fused QKV + G1

    qkv_gemm_kernel<<<grid4, 128, GEMM_SMEM_BYTES>>>(x, Wq, Wk, Wv, Wg);
    chunk_sums_kernel<<<NBLK, 256>>>();
    prefix_kernel<<<NBH * 16, 256>>>();
    chunk_out_kernel<<<NBLK, 256>>>();
    o_gemm_kernel<<<grid, 128, GEMM_SMEM_BYTES>>>(Wo, bo);
    gate_kernel<<<grid, 128, GEMM_SMEM_BYTES>>>(x, Wg, bg, out);
}